// round 2
// baseline (speedup 1.0000x reference)
#include <cuda_runtime.h>
#include <math.h>
#include <stdint.h>

#define NB 32
#define NT 512
#define NE 512
#define NH 512
#define NG 2048      // 4*H
#define NC 32
#define NF 1025      // 2H+1

// ---------------- static device scratch (allocation-free) ----------------
static __device__ float g_emb_out[NB * NT * NE];              // (B,T,E)
static __device__ float g_xw_f[(size_t)NB * NT * NG];         // (B,T,4H) fwd
static __device__ float g_xw_b[(size_t)NB * NT * NG];         // (B,T,4H) bwd
static __device__ float g_h1[(size_t)NB * NT * 2 * NH];       // layer0 out (B,T,2H)
static __device__ float g_h2[(size_t)NB * NT * 2 * NH];       // layer1 out (B,T,2H)
static __device__ float g_hstate[2][NH * NB];                 // [dir][unit*32 + b]
static __device__ float g_WcT[NF * NC];                       // transposed classifier W
static __device__ unsigned g_cnt[2];                          // group barrier counters

// ---------------- helpers ----------------
__device__ __forceinline__ unsigned ld_acq(const unsigned* p) {
    unsigned v;
    asm volatile("ld.acquire.gpu.global.b32 %0, [%1];" : "=r"(v) : "l"(p) : "memory");
    return v;
}
__device__ __forceinline__ float sigf(float x) { return 1.f / (1.f + expf(-x)); }

// ---------------- embedding gather ----------------
__global__ void k_embed(const int* __restrict__ x, const float* __restrict__ emb) {
    int bt = blockIdx.x;          // 0..16383
    int e4 = threadIdx.x;         // 0..127 (float4 index)
    int row = x[bt];
    reinterpret_cast<float4*>(g_emb_out)[(size_t)bt * 128 + e4] =
        reinterpret_cast<const float4*>(emb)[(size_t)row * 128 + e4];
}

// ---------------- input GEMM: C[M=16384][N=2048] = A[M][K] * W[N][K]^T + b1+b2 ----------------
// src_mode: 0 -> g_emb_out (K=512), 1 -> g_h1 (K=1024). dst_mode: 0 -> g_xw_f, 1 -> g_xw_b.
__global__ __launch_bounds__(256) void k_gemm(int src_mode, int dst_mode,
                                              const float* __restrict__ W,
                                              const float* __restrict__ b1,
                                              const float* __restrict__ b2,
                                              int K) {
    const float* __restrict__ A = (src_mode == 0) ? g_emb_out : g_h1;
    float* __restrict__ C = (dst_mode == 0) ? g_xw_f : g_xw_b;

    __shared__ float As[8][128];
    __shared__ float Bs[8][128];

    int tid = threadIdx.x;
    int m0 = blockIdx.y * 128;
    int n0 = blockIdx.x * 128;
    int tx = tid & 15;    // n subtile
    int ty = tid >> 4;    // m subtile

    float acc[8][8];
#pragma unroll
    for (int i = 0; i < 8; i++)
#pragma unroll
        for (int j = 0; j < 8; j++) acc[i][j] = 0.f;

    int lr = tid >> 1;          // 0..127 tile row
    int lc = (tid & 1) * 4;     // 0 or 4
    const float* Ap = A + (size_t)(m0 + lr) * K + lc;
    const float* Wp = W + (size_t)(n0 + lr) * K + lc;

    for (int k0 = 0; k0 < K; k0 += 8) {
        float4 av = *reinterpret_cast<const float4*>(Ap + k0);
        float4 wv = *reinterpret_cast<const float4*>(Wp + k0);
        As[lc + 0][lr] = av.x; As[lc + 1][lr] = av.y; As[lc + 2][lr] = av.z; As[lc + 3][lr] = av.w;
        Bs[lc + 0][lr] = wv.x; Bs[lc + 1][lr] = wv.y; Bs[lc + 2][lr] = wv.z; Bs[lc + 3][lr] = wv.w;
        __syncthreads();
#pragma unroll
        for (int k = 0; k < 8; k++) {
            float a[8], w[8];
            *reinterpret_cast<float4*>(a)     = *reinterpret_cast<float4*>(&As[k][ty * 8]);
            *reinterpret_cast<float4*>(a + 4) = *reinterpret_cast<float4*>(&As[k][ty * 8 + 4]);
            *reinterpret_cast<float4*>(w)     = *reinterpret_cast<float4*>(&Bs[k][tx * 8]);
            *reinterpret_cast<float4*>(w + 4) = *reinterpret_cast<float4*>(&Bs[k][tx * 8 + 4]);
#pragma unroll
            for (int i = 0; i < 8; i++)
#pragma unroll
                for (int j = 0; j < 8; j++) acc[i][j] += a[i] * w[j];
        }
        __syncthreads();
    }

    float bias[8];
#pragma unroll
    for (int j = 0; j < 8; j++) {
        int n = n0 + tx * 8 + j;
        bias[j] = b1[n] + b2[n];
    }
#pragma unroll
    for (int i = 0; i < 8; i++) {
        size_t base = (size_t)(m0 + ty * 8 + i) * NG + n0 + tx * 8;
        float4 v0 = make_float4(acc[i][0] + bias[0], acc[i][1] + bias[1],
                                acc[i][2] + bias[2], acc[i][3] + bias[3]);
        float4 v1 = make_float4(acc[i][4] + bias[4], acc[i][5] + bias[5],
                                acc[i][6] + bias[6], acc[i][7] + bias[7]);
        *reinterpret_cast<float4*>(&C[base])     = v0;
        *reinterpret_cast<float4*>(&C[base + 4]) = v1;
    }
}

// ---------------- barrier counter init ----------------
__global__ void k_init() {
    if (threadIdx.x < 2) g_cnt[threadIdx.x] = 0u;
}

// ---------------- recurrent scan (one layer, both directions) ----------------
// 128 blocks: 0..63 fwd, 64..127 bwd. Each block owns 8 hidden units (all 4 gates).
// smem: w_sm[512*32] + h_sm[512*32] + gate_sm[32*32] + c_sm[256] = 34048 floats.
__global__ __launch_bounds__(128) void k_scan(const float* __restrict__ Whh_f,
                                              const float* __restrict__ Whh_b,
                                              int layer) {
    extern __shared__ float sm[];
    float* w_sm    = sm;             // [k][c] 512x32
    float* h_sm    = sm + 16384;     // [k][b] 512x32
    float* gate_sm = sm + 32768;     // [c][b] 32x32
    float* c_sm    = sm + 33792;     // [uu][b] 8x32

    const int tid = threadIdx.x;
    const int grp = blockIdx.x >> 6;         // 0 fwd, 1 bwd
    const int ub  = blockIdx.x & 63;
    const int u0  = ub * 8;                  // first hidden unit owned

    const float* __restrict__ xw  = grp ? g_xw_b : g_xw_f;
    const float* __restrict__ Whh = grp ? Whh_b : Whh_f;
    float* __restrict__ out       = layer ? g_h2 : g_h1;
    float* hstate                 = g_hstate[grp];

    // load Whh slice transposed into smem: col c (0..31) -> row (c>>3)*512 + u0 + (c&7)
    {
        int c = tid >> 2;     // 0..31
        int q = tid & 3;      // k quarter
        int row = ((c >> 3) << 9) + u0 + (c & 7);
        const float* wp = Whh + (size_t)row * NH + q * 128;
#pragma unroll
        for (int i = 0; i < 128; i += 4) {
            float4 v = *reinterpret_cast<const float4*>(wp + i);
            int k = q * 128 + i;
            w_sm[(k + 0) * 32 + c] = v.x;
            w_sm[(k + 1) * 32 + c] = v.y;
            w_sm[(k + 2) * 32 + c] = v.z;
            w_sm[(k + 3) * 32 + c] = v.w;
        }
    }
    c_sm[tid] = 0.f;
    c_sm[tid + 128] = 0.f;
    __syncthreads();

    const int tb = tid & 7;     // batch group: batches 4*tb..4*tb+3
    const int tc = tid >> 3;    // col group: cols 2*tc, 2*tc+1
    const int c0 = tc * 2;
    const int gcol0 = ((c0 >> 3) << 9) + u0 + (c0 & 7);   // global gate column (even)

    unsigned target = 64u;
    for (int t = 0; t < NT; t++) {
        const int tt = grp ? (NT - 1 - t) : t;

        // acc init from precomputed input-GEMM gates
        float acc[4][2];
#pragma unroll
        for (int j = 0; j < 4; j++) {
            int b = tb * 4 + j;
            float2 v = *reinterpret_cast<const float2*>(
                xw + ((size_t)b * NT + tt) * NG + gcol0);
            acc[j][0] = v.x;
            acc[j][1] = v.y;
        }

        if (t > 0) {
            // stage h state: straight float4 copy (global layout == smem layout)
            const float4* src = reinterpret_cast<const float4*>(hstate);
            float4* dst = reinterpret_cast<float4*>(h_sm);
#pragma unroll
            for (int i = 0; i < 32; i++) dst[tid + i * 128] = __ldcg(src + tid + i * 128);
            __syncthreads();

#pragma unroll 8
            for (int k = 0; k < NH; k++) {
                float4 h4 = *reinterpret_cast<float4*>(&h_sm[k * 32 + tb * 4]);
                float2 w2 = *reinterpret_cast<float2*>(&w_sm[k * 32 + tc * 2]);
                acc[0][0] += h4.x * w2.x; acc[0][1] += h4.x * w2.y;
                acc[1][0] += h4.y * w2.x; acc[1][1] += h4.y * w2.y;
                acc[2][0] += h4.z * w2.x; acc[2][1] += h4.z * w2.y;
                acc[3][0] += h4.w * w2.x; acc[3][1] += h4.w * w2.y;
            }
        }

        // write gate pre-activations to smem
#pragma unroll
        for (int i = 0; i < 2; i++) {
            float4 v = make_float4(acc[0][i], acc[1][i], acc[2][i], acc[3][i]);
            *reinterpret_cast<float4*>(&gate_sm[(tc * 2 + i) * 32 + tb * 4]) = v;
        }
        __syncthreads();

        // activations + c/h update: 256 (b,uu) pairs over 128 threads
#pragma unroll
        for (int p = 0; p < 2; p++) {
            int idx = tid + p * 128;
            int b = idx & 31;
            int uu = idx >> 5;
            float gi = gate_sm[(0  + uu) * 32 + b];
            float gf = gate_sm[(8  + uu) * 32 + b];
            float gg = gate_sm[(16 + uu) * 32 + b];
            float go = gate_sm[(24 + uu) * 32 + b];
            float cprev = c_sm[uu * 32 + b];
            float cn = sigf(gf) * cprev + sigf(gi) * tanhf(gg);
            float h  = sigf(go) * tanhf(cn);
            c_sm[uu * 32 + b] = cn;
            hstate[(u0 + uu) * 32 + b] = h;
            out[((size_t)b * NT + tt) * (2 * NH) + grp * NH + u0 + uu] = h;
        }

        // group barrier (release h writes, acquire before next staging)
        __threadfence();
        __syncthreads();
        if (tid == 0) {
            atomicAdd(&g_cnt[grp], 1u);
            while (ld_acq(&g_cnt[grp]) < target) { __nanosleep(64); }
        }
        __syncthreads();
        target += 64u;
    }
}

// ---------------- classifier weight transpose ----------------
__global__ void k_wct(const float* __restrict__ Wc) {
    int i = blockIdx.x * 256 + threadIdx.x;
    if (i < NF * NC) {
        int f = i >> 5, c = i & 31;
        g_WcT[f * NC + c] = Wc[(size_t)c * NF + f];
    }
}

// ---------------- classifier + log-softmax, output transposed (B, C, T) ----------------
__global__ __launch_bounds__(256) void k_cls(const float* __restrict__ truth,
                                             const int* __restrict__ tf,
                                             const float* __restrict__ bc,
                                             float* __restrict__ outp) {
    int warp = threadIdx.x >> 5;
    int lane = threadIdx.x & 31;
    int pos = blockIdx.x * 8 + warp;      // 0..16383
    int b = pos >> 9, t = pos & 511;

    float acc = bc[lane];
    float past = 0.f;
    if (tf[0] != 0 && t > 0) past = truth[b * NT + t - 1];
    acc += past * g_WcT[lane];

    const float4* h4 = reinterpret_cast<const float4*>(g_h2 + ((size_t)b * NT + t) * (2 * NH));
    const float* wt = g_WcT + NC;
#pragma unroll 4
    for (int f4 = 0; f4 < 256; f4++) {
        float4 hv = h4[f4];
        int f = f4 * 4;
        acc += hv.x * wt[(f + 0) * NC + lane];
        acc += hv.y * wt[(f + 1) * NC + lane];
        acc += hv.z * wt[(f + 2) * NC + lane];
        acc += hv.w * wt[(f + 3) * NC + lane];
    }

    float m = acc;
#pragma unroll
    for (int o = 16; o > 0; o >>= 1) m = fmaxf(m, __shfl_xor_sync(0xffffffffu, m, o));
    float e = expf(acc - m);
    float s = e;
#pragma unroll
    for (int o = 16; o > 0; o >>= 1) s += __shfl_xor_sync(0xffffffffu, s, o);
    float y = acc - m - logf(s);

    outp[((size_t)b * NC + lane) * NT + t] = y;
}

// ---------------- launch ----------------
extern "C" void kernel_launch(void* const* d_in, const int* in_sizes, int n_in,
                              void* d_out, int out_size) {
    const int*   x     = (const int*)d_in[0];
    const float* truth = (const float*)d_in[1];
    const int*   tf    = (const int*)d_in[2];
    const float* emb   = (const float*)d_in[3];
    const float* Wih0f = (const float*)d_in[4];
    const float* Whh0f = (const float*)d_in[5];
    const float* bih0f = (const float*)d_in[6];
    const float* bhh0f = (const float*)d_in[7];
    const float* Wih0b = (const float*)d_in[8];
    const float* Whh0b = (const float*)d_in[9];
    const float* bih0b = (const float*)d_in[10];
    const float* bhh0b = (const float*)d_in[11];
    const float* Wih1f = (const float*)d_in[12];
    const float* Whh1f = (const float*)d_in[13];
    const float* bih1f = (const float*)d_in[14];
    const float* bhh1f = (const float*)d_in[15];
    const float* Wih1b = (const float*)d_in[16];
    const float* Whh1b = (const float*)d_in[17];
    const float* bih1b = (const float*)d_in[18];
    const float* bhh1b = (const float*)d_in[19];
    const float* Wc    = (const float*)d_in[20];
    const float* bc    = (const float*)d_in[21];

    const int scan_smem = 34048 * sizeof(float);   // 136192 B
    cudaFuncSetAttribute(k_scan, cudaFuncAttributeMaxDynamicSharedMemorySize, scan_smem);

    dim3 ggrid(16, 128);   // N tiles x M tiles

    k_embed<<<NB * NT, 128>>>(x, emb);

    // layer 0 input GEMMs (K = 512)
    k_gemm<<<ggrid, 256>>>(0, 0, Wih0f, bih0f, bhh0f, 512);
    k_gemm<<<ggrid, 256>>>(0, 1, Wih0b, bih0b, bhh0b, 512);
    k_init<<<1, 32>>>();
    k_scan<<<128, 128, scan_smem>>>(Whh0f, Whh0b, 0);

    // layer 1 input GEMMs (K = 1024)
    k_gemm<<<ggrid, 256>>>(1, 0, Wih1f, bih1f, bhh1f, 1024);
    k_gemm<<<ggrid, 256>>>(1, 1, Wih1b, bih1b, bhh1b, 1024);
    k_init<<<1, 32>>>();
    k_scan<<<128, 128, scan_smem>>>(Whh1f, Whh1b, 1);

    // classifier
    k_wct<<<(NF * NC + 255) / 256, 256>>>(Wc);
    k_cls<<<(NB * NT) / 8, 256>>>(truth, tf, bc, (float*)d_out);

    (void)in_sizes; (void)n_in; (void)out_size;
}

// round 5
// speedup vs baseline: 1.1951x; 1.1951x over previous
#include <cuda_runtime.h>
#include <cuda_bf16.h>
#include <math.h>
#include <stdint.h>

#define NB 32
#define NT 512
#define NE 512
#define NH 512
#define NG 2048      // 4*H
#define NC 32
#define NF 1025      // 2H+1
#define NM (NB * NT) // 16384 rows

// ---------------- static device scratch (allocation-free) ----------------
static __device__ __align__(16) __nv_bfloat16 g_Ahi[(size_t)NM * 1024];
static __device__ __align__(16) __nv_bfloat16 g_Alo[(size_t)NM * 1024];
static __device__ __align__(16) __nv_bfloat16 g_Whi[(size_t)NG * 1024];
static __device__ __align__(16) __nv_bfloat16 g_Wlo[(size_t)NG * 1024];
static __device__ float g_xw_f[(size_t)NM * NG];              // (B,T,4H) fwd
static __device__ float g_xw_b[(size_t)NM * NG];              // (B,T,4H) bwd
static __device__ float g_h1[(size_t)NM * 2 * NH];            // layer0 out
static __device__ float g_h2[(size_t)NM * 2 * NH];            // layer1 out
static __device__ float g_hstate[2][NH * NB];                 // [dir][unit*32 + b]
static __device__ float g_WcT[NF * NC];                       // transposed classifier W
static __device__ unsigned g_cnt[2];                          // group barrier counters

// ---------------- helpers ----------------
__device__ __forceinline__ unsigned ld_acq(const unsigned* p) {
    unsigned v;
    asm volatile("ld.acquire.gpu.global.b32 %0, [%1];" : "=r"(v) : "l"(p) : "memory");
    return v;
}
__device__ __forceinline__ float sigf(float x) { return 1.f / (1.f + expf(-x)); }
__device__ __forceinline__ void split_bf16(float v, __nv_bfloat16& hi, __nv_bfloat16& lo) {
    hi = __float2bfloat16(v);
    lo = __float2bfloat16(v - __bfloat162float(hi));
}
__device__ __forceinline__ uint32_t smem_to_u32(const void* p) {
    uint32_t a;
    asm("{ .reg .u64 t; cvta.to.shared.u64 t, %1; cvt.u32.u64 %0, t; }" : "=r"(a) : "l"(p));
    return a;
}
__device__ __forceinline__ void cp_async16(uint32_t sa, const void* ga) {
    asm volatile("cp.async.cg.shared.global [%0], [%1], 16;" :: "r"(sa), "l"(ga));
}
__device__ __forceinline__ void ldsm4(uint32_t& r0, uint32_t& r1, uint32_t& r2, uint32_t& r3,
                                      uint32_t addr) {
    asm volatile("ldmatrix.sync.aligned.m8n8.x4.shared.b16 {%0,%1,%2,%3}, [%4];"
                 : "=r"(r0), "=r"(r1), "=r"(r2), "=r"(r3) : "r"(addr));
}
__device__ __forceinline__ void mma16816(float* d, const uint32_t* a, const uint32_t* b) {
    asm volatile(
        "mma.sync.aligned.m16n8k16.row.col.f32.bf16.bf16.f32 "
        "{%0,%1,%2,%3}, {%4,%5,%6,%7}, {%8,%9}, {%0,%1,%2,%3};"
        : "+f"(d[0]), "+f"(d[1]), "+f"(d[2]), "+f"(d[3])
        : "r"(a[0]), "r"(a[1]), "r"(a[2]), "r"(a[3]), "r"(b[0]), "r"(b[1]));
}

// ---------------- embedding gather -> bf16 hi/lo (K=512) ----------------
__global__ void k_embed(const int* __restrict__ x, const float* __restrict__ emb) {
    int bt = blockIdx.x;
    int e4 = threadIdx.x;            // 0..127
    int row = x[bt];
    float4 v = reinterpret_cast<const float4*>(emb)[(size_t)row * 128 + e4];
    __nv_bfloat16 hi[4], lo[4];
    split_bf16(v.x, hi[0], lo[0]); split_bf16(v.y, hi[1], lo[1]);
    split_bf16(v.z, hi[2], lo[2]); split_bf16(v.w, hi[3], lo[3]);
    size_t o = (size_t)bt * 128 + e4;   // uint2 index
    reinterpret_cast<uint2*>(g_Ahi)[o] = *reinterpret_cast<uint2*>(hi);
    reinterpret_cast<uint2*>(g_Alo)[o] = *reinterpret_cast<uint2*>(lo);
}

// ---------------- weight fp32 -> bf16 hi/lo ----------------
__global__ void k_convW(const float* __restrict__ src, int n4) {
    int i = blockIdx.x * 256 + threadIdx.x;
    if (i >= n4) return;
    float4 v = reinterpret_cast<const float4*>(src)[i];
    __nv_bfloat16 hi[4], lo[4];
    split_bf16(v.x, hi[0], lo[0]); split_bf16(v.y, hi[1], lo[1]);
    split_bf16(v.z, hi[2], lo[2]); split_bf16(v.w, hi[3], lo[3]);
    reinterpret_cast<uint2*>(g_Whi)[i] = *reinterpret_cast<uint2*>(hi);
    reinterpret_cast<uint2*>(g_Wlo)[i] = *reinterpret_cast<uint2*>(lo);
}

// ---------------- layer0 output fp32 -> bf16 hi/lo ----------------
__global__ void k_convA(int n4) {
    int i = blockIdx.x * 256 + threadIdx.x;
    if (i >= n4) return;
    float4 v = reinterpret_cast<const float4*>(g_h1)[i];
    __nv_bfloat16 hi[4], lo[4];
    split_bf16(v.x, hi[0], lo[0]); split_bf16(v.y, hi[1], lo[1]);
    split_bf16(v.z, hi[2], lo[2]); split_bf16(v.w, hi[3], lo[3]);
    reinterpret_cast<uint2*>(g_Ahi)[i] = *reinterpret_cast<uint2*>(hi);
    reinterpret_cast<uint2*>(g_Alo)[i] = *reinterpret_cast<uint2*>(lo);
}

// ---------------- HMMA input GEMM ----------------
// C[16384][2048] = A*W^T + b1 + b2, bf16 hi/lo 3-term split, fp32 accum.
// 128x128 tile, BK=32, 256 threads (8 warps 4Mx2N), cp.async double buffer.
// Smem rows padded to 40 bf16 (80B): ldmatrix phases hit all 32 banks once.
#define SKP 40
#define TILE_B (128 * SKP * 2)       // 10240 B per tile
#define BUF_B (4 * TILE_B)           // 40960 B per stage
#define GSMEM (2 * BUF_B)            // 81920 B

__global__ __launch_bounds__(256, 1) void k_gemm_bf16(int dst_mode,
                                                      const float* __restrict__ b1,
                                                      const float* __restrict__ b2,
                                                      int K) {
    extern __shared__ __align__(16) char smem[];
    uint32_t sb = smem_to_u32(smem);
    float* __restrict__ C = dst_mode ? g_xw_b : g_xw_f;

    const int tid = threadIdx.x;
    const int lane = tid & 31;
    const int wid = tid >> 5;
    const int wm = wid & 3;          // warp M index (32 rows each)
    const int wn = wid >> 2;         // warp N index (64 cols each)
    const int n0 = blockIdx.x * 128;
    const int m0 = blockIdx.y * 128;

    float d[2][8][4];
#pragma unroll
    for (int mt = 0; mt < 2; mt++)
#pragma unroll
        for (int nt = 0; nt < 8; nt++)
#pragma unroll
            for (int q = 0; q < 4; q++) d[mt][nt][q] = 0.f;

    const int r_ld = tid >> 2;       // shared load row helper
    const int s_ld = tid & 3;

    // ---- async chunk loader: 4 tiles x 128 rows x 64B ----
    auto load_chunk = [&](int ch, int buf) {
        const int k0 = ch << 5;
        const uint32_t sbb = sb + buf * BUF_B;
#pragma unroll
        for (int tile = 0; tile < 4; tile++) {
            const __nv_bfloat16* gsrc =
                tile == 0 ? g_Ahi : tile == 1 ? g_Alo : tile == 2 ? g_Whi : g_Wlo;
            const int base = tile < 2 ? m0 : n0;
#pragma unroll
            for (int half = 0; half < 2; half++) {
                int idx = half * 256 + tid;          // 0..511
                int r = idx >> 2, s = idx & 3;
                const void* ga = gsrc + (size_t)(base + r) * K + k0 + s * 8;
                cp_async16(sbb + tile * TILE_B + r * (SKP * 2) + s * 16, ga);
            }
        }
        asm volatile("cp.async.commit_group;" ::: "memory");
    };

    const int nch = K >> 5;
    load_chunk(0, 0);

    for (int ch = 0; ch < nch; ch++) {
        if (ch + 1 < nch) {
            load_chunk(ch + 1, (ch + 1) & 1);
            asm volatile("cp.async.wait_group 1;" ::: "memory");
        } else {
            asm volatile("cp.async.wait_group 0;" ::: "memory");
        }
        __syncthreads();

        const uint32_t Ah = sb + (ch & 1) * BUF_B;
        const uint32_t Al = Ah + TILE_B;
        const uint32_t Wh = Ah + 2 * TILE_B;
        const uint32_t Wl = Ah + 3 * TILE_B;

#pragma unroll
        for (int k16 = 0; k16 < 2; k16++) {
            const int kb = k16 * 32;       // byte offset (16 bf16)

            uint32_t ahi[2][4], alo[2][4];
#pragma unroll
            for (int mt = 0; mt < 2; mt++) {
                uint32_t addr = Ah + (wm * 32 + mt * 16 + (lane & 15)) * (SKP * 2)
                                + ((lane >> 4) << 4) + kb;
                ldsm4(ahi[mt][0], ahi[mt][1], ahi[mt][2], ahi[mt][3], addr);
                ldsm4(alo[mt][0], alo[mt][1], alo[mt][2], alo[mt][3], addr + TILE_B);
            }

            uint32_t bhi[8][2], blo[8][2];
#pragma unroll
            for (int j = 0; j < 4; j++) {
                uint32_t addr = Wh + (wn * 64 + j * 16 + (lane & 7) + ((lane >> 4) << 3)) * (SKP * 2)
                                + (((lane >> 3) & 1) << 4) + kb;
                uint32_t r0, r1, r2, r3;
                ldsm4(r0, r1, r2, r3, addr);
                bhi[2 * j][0] = r0; bhi[2 * j][1] = r1;
                bhi[2 * j + 1][0] = r2; bhi[2 * j + 1][1] = r3;
                ldsm4(r0, r1, r2, r3, addr + TILE_B);
                blo[2 * j][0] = r0; blo[2 * j][1] = r1;
                blo[2 * j + 1][0] = r2; blo[2 * j + 1][1] = r3;
            }

#pragma unroll
            for (int mt = 0; mt < 2; mt++)
#pragma unroll
                for (int nt = 0; nt < 8; nt++) {
                    mma16816(d[mt][nt], ahi[mt], bhi[nt]);   // hi*hi
                    mma16816(d[mt][nt], ahi[mt], blo[nt]);   // hi*lo
                    mma16816(d[mt][nt], alo[mt], bhi[nt]);   // lo*hi
                }
        }
        __syncthreads();
    }

    // ---- epilogue: bias add + writeback ----
#pragma unroll
    for (int nt = 0; nt < 8; nt++) {
        int n = n0 + wn * 64 + nt * 8 + 2 * (lane & 3);
        float bx = b1[n] + b2[n];
        float by = b1[n + 1] + b2[n + 1];
#pragma unroll
        for (int mt = 0; mt < 2; mt++) {
            int m = m0 + wm * 32 + mt * 16 + (lane >> 2);
            float2 v0 = make_float2(d[mt][nt][0] + bx, d[mt][nt][1] + by);
            float2 v1 = make_float2(d[mt][nt][2] + bx, d[mt][nt][3] + by);
            *reinterpret_cast<float2*>(&C[(size_t)m * NG + n]) = v0;
            *reinterpret_cast<float2*>(&C[(size_t)(m + 8) * NG + n]) = v1;
        }
    }
    (void)r_ld; (void)s_ld;
}

// ---------------- barrier counter init ----------------
__global__ void k_init() {
    if (threadIdx.x < 2) g_cnt[threadIdx.x] = 0u;
}

// ---------------- recurrent scan (unchanged from passing R2 kernel) ----------------
__global__ __launch_bounds__(128) void k_scan(const float* __restrict__ Whh_f,
                                              const float* __restrict__ Whh_b,
                                              int layer) {
    extern __shared__ float sm[];
    float* w_sm    = sm;             // [k][c] 512x32
    float* h_sm    = sm + 16384;     // [k][b] 512x32
    float* gate_sm = sm + 32768;     // [c][b] 32x32
    float* c_sm    = sm + 33792;     // [uu][b] 8x32

    const int tid = threadIdx.x;
    const int grp = blockIdx.x >> 6;
    const int ub  = blockIdx.x & 63;
    const int u0  = ub * 8;

    const float* __restrict__ xw  = grp ? g_xw_b : g_xw_f;
    const float* __restrict__ Whh = grp ? Whh_b : Whh_f;
    float* __restrict__ out       = layer ? g_h2 : g_h1;
    float* hstate                 = g_hstate[grp];

    {
        int c = tid >> 2;
        int q = tid & 3;
        int row = ((c >> 3) << 9) + u0 + (c & 7);
        const float* wp = Whh + (size_t)row * NH + q * 128;
#pragma unroll
        for (int i = 0; i < 128; i += 4) {
            float4 v = *reinterpret_cast<const float4*>(wp + i);
            int k = q * 128 + i;
            w_sm[(k + 0) * 32 + c] = v.x;
            w_sm[(k + 1) * 32 + c] = v.y;
            w_sm[(k + 2) * 32 + c] = v.z;
            w_sm[(k + 3) * 32 + c] = v.w;
        }
    }
    c_sm[tid] = 0.f;
    c_sm[tid + 128] = 0.f;
    __syncthreads();

    const int tb = tid & 7;
    const int tc = tid >> 3;
    const int c0 = tc * 2;
    const int gcol0 = ((c0 >> 3) << 9) + u0 + (c0 & 7);

    unsigned target = 64u;
    for (int t = 0; t < NT; t++) {
        const int tt = grp ? (NT - 1 - t) : t;

        float acc[4][2];
#pragma unroll
        for (int j = 0; j < 4; j++) {
            int b = tb * 4 + j;
            float2 v = *reinterpret_cast<const float2*>(
                xw + ((size_t)b * NT + tt) * NG + gcol0);
            acc[j][0] = v.x;
            acc[j][1] = v.y;
        }

        if (t > 0) {
            const float4* src = reinterpret_cast<const float4*>(hstate);
            float4* dst = reinterpret_cast<float4*>(h_sm);
#pragma unroll
            for (int i = 0; i < 32; i++) dst[tid + i * 128] = __ldcg(src + tid + i * 128);
            __syncthreads();

#pragma unroll 8
            for (int k = 0; k < NH; k++) {
                float4 h4 = *reinterpret_cast<float4*>(&h_sm[k * 32 + tb * 4]);
                float2 w2 = *reinterpret_cast<float2*>(&w_sm[k * 32 + tc * 2]);
                acc[0][0] += h4.x * w2.x; acc[0][1] += h4.x * w2.y;
                acc[1][0] += h4.y * w2.x; acc[1][1] += h4.y * w2.y;
                acc[2][0] += h4.z * w2.x; acc[2][1] += h4.z * w2.y;
                acc[3][0] += h4.w * w2.x; acc[3][1] += h4.w * w2.y;
            }
        }

#pragma unroll
        for (int i = 0; i < 2; i++) {
            float4 v = make_float4(acc[0][i], acc[1][i], acc[2][i], acc[3][i]);
            *reinterpret_cast<float4*>(&gate_sm[(tc * 2 + i) * 32 + tb * 4]) = v;
        }
        __syncthreads();

#pragma unroll
        for (int p = 0; p < 2; p++) {
            int idx = tid + p * 128;
            int b = idx & 31;
            int uu = idx >> 5;
            float gi = gate_sm[(0  + uu) * 32 + b];
            float gf = gate_sm[(8  + uu) * 32 + b];
            float gg = gate_sm[(16 + uu) * 32 + b];
            float go = gate_sm[(24 + uu) * 32 + b];
            float cprev = c_sm[uu * 32 + b];
            float cn = sigf(gf) * cprev + sigf(gi) * tanhf(gg);
            float h  = sigf(go) * tanhf(cn);
            c_sm[uu * 32 + b] = cn;
            hstate[(u0 + uu) * 32 + b] = h;
            out[((size_t)b * NT + tt) * (2 * NH) + grp * NH + u0 + uu] = h;
        }

        __threadfence();
        __syncthreads();
        if (tid == 0) {
            atomicAdd(&g_cnt[grp], 1u);
            while (ld_acq(&g_cnt[grp]) < target) { __nanosleep(64); }
        }
        __syncthreads();
        target += 64u;
    }
}

// ---------------- classifier weight transpose ----------------
__global__ void k_wct(const float* __restrict__ Wc) {
    int i = blockIdx.x * 256 + threadIdx.x;
    if (i < NF * NC) {
        int f = i >> 5, c = i & 31;
        g_WcT[f * NC + c] = Wc[(size_t)c * NF + f];
    }
}

// ---------------- classifier + log-softmax, output (B, C, T) ----------------
__global__ __launch_bounds__(256) void k_cls(const float* __restrict__ truth,
                                             const int* __restrict__ tf,
                                             const float* __restrict__ bc,
                                             float* __restrict__ outp) {
    int warp = threadIdx.x >> 5;
    int lane = threadIdx.x & 31;
    int pos = blockIdx.x * 8 + warp;
    int b = pos >> 9, t = pos & 511;

    float acc = bc[lane];
    float past = 0.f;
    if (tf[0] != 0 && t > 0) past = truth[b * NT + t - 1];
    acc += past * g_WcT[lane];

    const float4* h4 = reinterpret_cast<const float4*>(g_h2 + ((size_t)b * NT + t) * (2 * NH));
    const float* wt = g_WcT + NC;
#pragma unroll 4
    for (int f4 = 0; f4 < 256; f4++) {
        float4 hv = h4[f4];
        int f = f4 * 4;
        acc += hv.x * wt[(f + 0) * NC + lane];
        acc += hv.y * wt[(f + 1) * NC + lane];
        acc += hv.z * wt[(f + 2) * NC + lane];
        acc += hv.w * wt[(f + 3) * NC + lane];
    }

    float m = acc;
#pragma unroll
    for (int o = 16; o > 0; o >>= 1) m = fmaxf(m, __shfl_xor_sync(0xffffffffu, m, o));
    float e = expf(acc - m);
    float s = e;
#pragma unroll
    for (int o = 16; o > 0; o >>= 1) s += __shfl_xor_sync(0xffffffffu, s, o);
    float y = acc - m - logf(s);

    outp[((size_t)b * NC + lane) * NT + t] = y;
}

// ---------------- launch ----------------
extern "C" void kernel_launch(void* const* d_in, const int* in_sizes, int n_in,
                              void* d_out, int out_size) {
    const int*   x     = (const int*)d_in[0];
    const float* truth = (const float*)d_in[1];
    const int*   tf    = (const int*)d_in[2];
    const float* emb   = (const float*)d_in[3];
    const float* Wih0f = (const float*)d_in[4];
    const float* Whh0f = (const float*)d_in[5];
    const float* bih0f = (const float*)d_in[6];
    const float* bhh0f = (const float*)d_in[7];
    const float* Wih0b = (const float*)d_in[8];
    const float* Whh0b = (const float*)d_in[9];
    const float* bih0b = (const float*)d_in[10];
    const float* bhh0b = (const float*)d_in[11];
    const float* Wih1f = (const float*)d_in[12];
    const float* Whh1f = (const float*)d_in[13];
    const float* bih1f = (const float*)d_in[14];
    const float* bhh1f = (const float*)d_in[15];
    const float* Wih1b = (const float*)d_in[16];
    const float* Whh1b = (const float*)d_in[17];
    const float* bih1b = (const float*)d_in[18];
    const float* bhh1b = (const float*)d_in[19];
    const float* Wc    = (const float*)d_in[20];
    const float* bc    = (const float*)d_in[21];

    const int scan_smem = 34048 * sizeof(float);   // 136192 B
    cudaFuncSetAttribute(k_scan, cudaFuncAttributeMaxDynamicSharedMemorySize, scan_smem);
    cudaFuncSetAttribute(k_gemm_bf16, cudaFuncAttributeMaxDynamicSharedMemorySize, GSMEM);

    dim3 ggrid(16, 128);     // n-tiles x m-tiles
    const int w0_n4 = NG * 512 / 4;
    const int w1_n4 = NG * 1024 / 4;
    const int a1_n4 = NM * 1024 / 4;

    // ---- layer 0 (K = 512) ----
    k_embed<<<NM, 128>>>(x, emb);                                   // -> g_Ahi/g_Alo
    k_init<<<1, 32>>>();
    k_convW<<<(w0_n4 + 255) / 256, 256>>>(Wih0f, w0_n4);
    k_gemm_bf16<<<ggrid, 256, GSMEM>>>(0, bih0f, bhh0f, 512);
    k_convW<<<(w0_n4 + 255) / 256, 256>>>(Wih0b, w0_n4);
    k_gemm_bf16<<<ggrid, 256, GSMEM>>>(1, bih0b, bhh0b, 512);
    k_scan<<<128, 128, scan_smem>>>(Whh0f, Whh0b, 0);

    // ---- layer 1 (K = 1024) ----
    k_convA<<<(a1_n4 + 255) / 256, 256>>>(a1_n4);                   // g_h1 -> g_Ahi/g_Alo
    k_init<<<1, 32>>>();
    k_convW<<<(w1_n4 + 255) / 256, 256>>>(Wih1f, w1_n4);
    k_gemm_bf16<<<ggrid, 256, GSMEM>>>(0, bih1f, bhh1f, 1024);
    k_convW<<<(w1_n4 + 255) / 256, 256>>>(Wih1b, w1_n4);
    k_gemm_bf16<<<ggrid, 256, GSMEM>>>(1, bih1b, bhh1b, 1024);
    k_scan<<<128, 128, scan_smem>>>(Whh1f, Whh1b, 1);

    // ---- classifier ----
    k_wct<<<(NF * NC + 255) / 256, 256>>>(Wc);
    k_cls<<<NM / 8, 256>>>(truth, tf, bc, (float*)d_out);

    (void)in_sizes; (void)n_in; (void)out_size;
}

// round 6
// speedup vs baseline: 1.8692x; 1.5640x over previous
#include <cuda_runtime.h>
#include <cuda_bf16.h>
#include <math.h>
#include <stdint.h>

#define NB 32
#define NT 512
#define NE 512
#define NH 512
#define NG 2048      // 4*H
#define NC 32
#define NF 1025      // 2H+1
#define NM (NB * NT) // 16384 rows

// ---------------- static device scratch (allocation-free) ----------------
static __device__ __align__(16) __nv_bfloat16 g_Ahi[(size_t)NM * 1024];
static __device__ __align__(16) __nv_bfloat16 g_Alo[(size_t)NM * 1024];
static __device__ __align__(16) __nv_bfloat16 g_Whi[(size_t)NG * 1024];
static __device__ __align__(16) __nv_bfloat16 g_Wlo[(size_t)NG * 1024];
static __device__ float g_xw_f[(size_t)NM * NG];              // (B,T,4H) fwd
static __device__ float g_xw_b[(size_t)NM * NG];              // (B,T,4H) bwd
static __device__ float g_h1[(size_t)NM * 2 * NH];            // layer0 out
static __device__ float g_h2[(size_t)NM * 2 * NH];            // layer1 out
static __device__ __align__(16) __nv_bfloat16 g_hb_hi[2][NB * NH];  // [dir][b*512+u]
static __device__ __align__(16) __nv_bfloat16 g_hb_lo[2][NB * NH];
static __device__ float g_WcT[NF * NC];                       // transposed classifier W
static __device__ unsigned g_cnt[2];                          // group barrier counters

// ---------------- helpers ----------------
__device__ __forceinline__ unsigned ld_acq(const unsigned* p) {
    unsigned v;
    asm volatile("ld.acquire.gpu.global.b32 %0, [%1];" : "=r"(v) : "l"(p) : "memory");
    return v;
}
__device__ __forceinline__ float sigf(float x) { return 1.f / (1.f + expf(-x)); }
__device__ __forceinline__ void split_bf16(float v, __nv_bfloat16& hi, __nv_bfloat16& lo) {
    hi = __float2bfloat16(v);
    lo = __float2bfloat16(v - __bfloat162float(hi));
}
__device__ __forceinline__ uint32_t smem_to_u32(const void* p) {
    uint32_t a;
    asm("{ .reg .u64 t; cvta.to.shared.u64 t, %1; cvt.u32.u64 %0, t; }" : "=r"(a) : "l"(p));
    return a;
}
__device__ __forceinline__ void cp_async16(uint32_t sa, const void* ga) {
    asm volatile("cp.async.cg.shared.global [%0], [%1], 16;" :: "r"(sa), "l"(ga));
}
__device__ __forceinline__ void ldsm4(uint32_t& r0, uint32_t& r1, uint32_t& r2, uint32_t& r3,
                                      uint32_t addr) {
    asm volatile("ldmatrix.sync.aligned.m8n8.x4.shared.b16 {%0,%1,%2,%3}, [%4];"
                 : "=r"(r0), "=r"(r1), "=r"(r2), "=r"(r3) : "r"(addr));
}
__device__ __forceinline__ void mma16816(float* d, const uint32_t* a, const uint32_t* b) {
    asm volatile(
        "mma.sync.aligned.m16n8k16.row.col.f32.bf16.bf16.f32 "
        "{%0,%1,%2,%3}, {%4,%5,%6,%7}, {%8,%9}, {%0,%1,%2,%3};"
        : "+f"(d[0]), "+f"(d[1]), "+f"(d[2]), "+f"(d[3])
        : "r"(a[0]), "r"(a[1]), "r"(a[2]), "r"(a[3]), "r"(b[0]), "r"(b[1]));
}

// ---------------- embedding gather -> bf16 hi/lo (K=512) ----------------
__global__ void k_embed(const int* __restrict__ x, const float* __restrict__ emb) {
    int bt = blockIdx.x;
    int e4 = threadIdx.x;            // 0..127
    int row = x[bt];
    float4 v = reinterpret_cast<const float4*>(emb)[(size_t)row * 128 + e4];
    __nv_bfloat16 hi[4], lo[4];
    split_bf16(v.x, hi[0], lo[0]); split_bf16(v.y, hi[1], lo[1]);
    split_bf16(v.z, hi[2], lo[2]); split_bf16(v.w, hi[3], lo[3]);
    size_t o = (size_t)bt * 128 + e4;   // uint2 index
    reinterpret_cast<uint2*>(g_Ahi)[o] = *reinterpret_cast<uint2*>(hi);
    reinterpret_cast<uint2*>(g_Alo)[o] = *reinterpret_cast<uint2*>(lo);
}

// ---------------- weight fp32 -> bf16 hi/lo ----------------
__global__ void k_convW(const float* __restrict__ src, int n4) {
    int i = blockIdx.x * 256 + threadIdx.x;
    if (i >= n4) return;
    float4 v = reinterpret_cast<const float4*>(src)[i];
    __nv_bfloat16 hi[4], lo[4];
    split_bf16(v.x, hi[0], lo[0]); split_bf16(v.y, hi[1], lo[1]);
    split_bf16(v.z, hi[2], lo[2]); split_bf16(v.w, hi[3], lo[3]);
    reinterpret_cast<uint2*>(g_Whi)[i] = *reinterpret_cast<uint2*>(hi);
    reinterpret_cast<uint2*>(g_Wlo)[i] = *reinterpret_cast<uint2*>(lo);
}

// ---------------- layer0 output fp32 -> bf16 hi/lo ----------------
__global__ void k_convA(int n4) {
    int i = blockIdx.x * 256 + threadIdx.x;
    if (i >= n4) return;
    float4 v = reinterpret_cast<const float4*>(g_h1)[i];
    __nv_bfloat16 hi[4], lo[4];
    split_bf16(v.x, hi[0], lo[0]); split_bf16(v.y, hi[1], lo[1]);
    split_bf16(v.z, hi[2], lo[2]); split_bf16(v.w, hi[3], lo[3]);
    reinterpret_cast<uint2*>(g_Ahi)[i] = *reinterpret_cast<uint2*>(hi);
    reinterpret_cast<uint2*>(g_Alo)[i] = *reinterpret_cast<uint2*>(lo);
}

// ---------------- HMMA input GEMM (unchanged from passing R5) ----------------
#define SKP 40
#define TILE_B (128 * SKP * 2)       // 10240 B per tile
#define BUF_B (4 * TILE_B)           // 40960 B per stage
#define GSMEM (2 * BUF_B)            // 81920 B

__global__ __launch_bounds__(256, 1) void k_gemm_bf16(int dst_mode,
                                                      const float* __restrict__ b1,
                                                      const float* __restrict__ b2,
                                                      int K) {
    extern __shared__ __align__(16) char smem[];
    uint32_t sb = smem_to_u32(smem);
    float* __restrict__ C = dst_mode ? g_xw_b : g_xw_f;

    const int tid = threadIdx.x;
    const int lane = tid & 31;
    const int wid = tid >> 5;
    const int wm = wid & 3;
    const int wn = wid >> 2;
    const int n0 = blockIdx.x * 128;
    const int m0 = blockIdx.y * 128;

    float d[2][8][4];
#pragma unroll
    for (int mt = 0; mt < 2; mt++)
#pragma unroll
        for (int nt = 0; nt < 8; nt++)
#pragma unroll
            for (int q = 0; q < 4; q++) d[mt][nt][q] = 0.f;

    auto load_chunk = [&](int ch, int buf) {
        const int k0 = ch << 5;
        const uint32_t sbb = sb + buf * BUF_B;
#pragma unroll
        for (int tile = 0; tile < 4; tile++) {
            const __nv_bfloat16* gsrc =
                tile == 0 ? g_Ahi : tile == 1 ? g_Alo : tile == 2 ? g_Whi : g_Wlo;
            const int base = tile < 2 ? m0 : n0;
#pragma unroll
            for (int half = 0; half < 2; half++) {
                int idx = half * 256 + tid;
                int r = idx >> 2, s = idx & 3;
                const void* ga = gsrc + (size_t)(base + r) * K + k0 + s * 8;
                cp_async16(sbb + tile * TILE_B + r * (SKP * 2) + s * 16, ga);
            }
        }
        asm volatile("cp.async.commit_group;" ::: "memory");
    };

    const int nch = K >> 5;
    load_chunk(0, 0);

    for (int ch = 0; ch < nch; ch++) {
        if (ch + 1 < nch) {
            load_chunk(ch + 1, (ch + 1) & 1);
            asm volatile("cp.async.wait_group 1;" ::: "memory");
        } else {
            asm volatile("cp.async.wait_group 0;" ::: "memory");
        }
        __syncthreads();

        const uint32_t Ah = sb + (ch & 1) * BUF_B;
        const uint32_t Wh = Ah + 2 * TILE_B;

#pragma unroll
        for (int k16 = 0; k16 < 2; k16++) {
            const int kb = k16 * 32;

            uint32_t ahi[2][4], alo[2][4];
#pragma unroll
            for (int mt = 0; mt < 2; mt++) {
                uint32_t addr = Ah + (wm * 32 + mt * 16 + (lane & 15)) * (SKP * 2)
                                + ((lane >> 4) << 4) + kb;
                ldsm4(ahi[mt][0], ahi[mt][1], ahi[mt][2], ahi[mt][3], addr);
                ldsm4(alo[mt][0], alo[mt][1], alo[mt][2], alo[mt][3], addr + TILE_B);
            }

            uint32_t bhi[8][2], blo[8][2];
#pragma unroll
            for (int j = 0; j < 4; j++) {
                uint32_t addr = Wh + (wn * 64 + j * 16 + (lane & 7) + ((lane >> 4) << 3)) * (SKP * 2)
                                + (((lane >> 3) & 1) << 4) + kb;
                uint32_t r0, r1, r2, r3;
                ldsm4(r0, r1, r2, r3, addr);
                bhi[2 * j][0] = r0; bhi[2 * j][1] = r1;
                bhi[2 * j + 1][0] = r2; bhi[2 * j + 1][1] = r3;
                ldsm4(r0, r1, r2, r3, addr + TILE_B);
                blo[2 * j][0] = r0; blo[2 * j][1] = r1;
                blo[2 * j + 1][0] = r2; blo[2 * j + 1][1] = r3;
            }

#pragma unroll
            for (int mt = 0; mt < 2; mt++)
#pragma unroll
                for (int nt = 0; nt < 8; nt++) {
                    mma16816(d[mt][nt], ahi[mt], bhi[nt]);
                    mma16816(d[mt][nt], ahi[mt], blo[nt]);
                    mma16816(d[mt][nt], alo[mt], bhi[nt]);
                }
        }
        __syncthreads();
    }

#pragma unroll
    for (int nt = 0; nt < 8; nt++) {
        int n = n0 + wn * 64 + nt * 8 + 2 * (lane & 3);
        float bx = b1[n] + b2[n];
        float by = b1[n + 1] + b2[n + 1];
#pragma unroll
        for (int mt = 0; mt < 2; mt++) {
            int m = m0 + wm * 32 + mt * 16 + (lane >> 2);
            float2 v0 = make_float2(d[mt][nt][0] + bx, d[mt][nt][1] + by);
            float2 v1 = make_float2(d[mt][nt][2] + bx, d[mt][nt][3] + by);
            *reinterpret_cast<float2*>(&C[(size_t)m * NG + n]) = v0;
            *reinterpret_cast<float2*>(&C[(size_t)(m + 8) * NG + n]) = v1;
        }
    }
}

// ---------------- barrier counter init ----------------
__global__ void k_init() {
    if (threadIdx.x < 2) g_cnt[threadIdx.x] = 0u;
}

// ---------------- tensor-core recurrent scan ----------------
// 64 blocks: 0..31 fwd, 32..63 bwd. Each block owns 16 hidden units = 64 gate rows.
// Per step: D(64x32) = WhhSlice(64x512) . h^T via bf16 hi/lo 3-term HMMA.
// Whh slice resident in smem bf16 hi/lo; h staged from global bf16 hi/lo.
#define SPITCH 1040                    // 520 bf16 per row (ldmatrix conflict-free)
#define OFF_AHI 0
#define OFF_ALO (OFF_AHI + 64 * SPITCH)      // 66560
#define OFF_BHI (OFF_ALO + 64 * SPITCH)      // 133120
#define OFF_BLO (OFF_BHI + 32 * SPITCH)      // 166400
#define OFF_D   (OFF_BLO + 32 * SPITCH)      // 199680  (64 x 34 fp32)
#define OFF_C   (OFF_D + 64 * 34 * 4)        // 208384  (16 x 34 fp32)
#define SCAN_SMEM (OFF_C + 16 * 34 * 4)      // 210560

__global__ __launch_bounds__(256, 1) void k_scan_tc(const float* __restrict__ Whh_f,
                                                    const float* __restrict__ Whh_b,
                                                    int layer) {
    extern __shared__ __align__(16) char smem[];
    const uint32_t sb = smem_to_u32(smem);
    float* const Dp = reinterpret_cast<float*>(smem + OFF_D);
    float* const Cp = reinterpret_cast<float*>(smem + OFF_C);

    const int tid = threadIdx.x;
    const int lane = tid & 31;
    const int wid = tid >> 5;
    const int mtw = wid & 3;          // warp m-tile (16 gate rows)
    const int ntw = wid >> 2;         // warp n-tile (16 batches)
    const int grp = blockIdx.x >> 5;  // 0 fwd, 1 bwd
    const int ub  = blockIdx.x & 31;
    const int u0  = ub * 16;          // first owned hidden unit

    const float* __restrict__ xw  = grp ? g_xw_b : g_xw_f;
    const float* __restrict__ Whh = grp ? Whh_b : Whh_f;
    float* __restrict__ out       = layer ? g_h2 : g_h1;
    __nv_bfloat16* const hb_hi = g_hb_hi[grp];
    __nv_bfloat16* const hb_lo = g_hb_lo[grp];

    // ---- init: Whh slice -> smem bf16 hi/lo; zero D; zero c ----
    {
        int m = tid >> 2;                 // 0..63 slice row
        int kq = (tid & 3) * 128;         // k quarter
        int gcol = ((m >> 4) << 9) + u0 + (m & 15);
        const float4* wp = reinterpret_cast<const float4*>(Whh + (size_t)gcol * NH + kq);
        char* arow_hi = smem + OFF_AHI + m * SPITCH + kq * 2;
        char* arow_lo = smem + OFF_ALO + m * SPITCH + kq * 2;
#pragma unroll
        for (int i = 0; i < 32; i++) {
            float4 v = wp[i];
            __nv_bfloat16 hi[4], lo[4];
            split_bf16(v.x, hi[0], lo[0]); split_bf16(v.y, hi[1], lo[1]);
            split_bf16(v.z, hi[2], lo[2]); split_bf16(v.w, hi[3], lo[3]);
            *reinterpret_cast<uint2*>(arow_hi + i * 8) = *reinterpret_cast<uint2*>(hi);
            *reinterpret_cast<uint2*>(arow_lo + i * 8) = *reinterpret_cast<uint2*>(lo);
        }
        for (int i = tid; i < 64 * 34; i += 256) Dp[i] = 0.f;
        for (int i = tid; i < 16 * 34; i += 256) Cp[i] = 0.f;
    }
    __syncthreads();

    // ldmatrix base addresses (R5-verified fragment mappings, pitch = SPITCH)
    const uint32_t a_base_hi = sb + OFF_AHI + (mtw * 16 + (lane & 15)) * SPITCH + ((lane >> 4) << 4);
    const uint32_t a_base_lo = a_base_hi + (OFF_ALO - OFF_AHI);
    const uint32_t b_base_hi = sb + OFF_BHI
        + (ntw * 16 + (lane & 7) + ((lane >> 4) << 3)) * SPITCH + (((lane >> 3) & 1) << 4);
    const uint32_t b_base_lo = b_base_hi + (OFF_BLO - OFF_BHI);

    unsigned target = 32u;
    for (int t = 0; t < NT; t++) {
        const int tt = grp ? (NT - 1 - t) : t;

        if (t > 0) {
            // ---- stage h (bf16 hi/lo) global -> smem, repad rows to SPITCH ----
#pragma unroll
            for (int i = 0; i < 8; i++) {
                int idx = i * 256 + tid;          // 0..2047 (32 rows x 64 chunks)
                int b = idx >> 6, c = idx & 63;
                uint4 vhi = __ldcg(reinterpret_cast<const uint4*>(hb_hi + b * NH + c * 8));
                uint4 vlo = __ldcg(reinterpret_cast<const uint4*>(hb_lo + b * NH + c * 8));
                *reinterpret_cast<uint4*>(smem + OFF_BHI + b * SPITCH + c * 16) = vhi;
                *reinterpret_cast<uint4*>(smem + OFF_BLO + b * SPITCH + c * 16) = vlo;
            }
            __syncthreads();

            // ---- HMMA: D(64x32) += Whh . h^T, 3-term split ----
            float df[2][4];
#pragma unroll
            for (int nt = 0; nt < 2; nt++)
#pragma unroll
                for (int q = 0; q < 4; q++) df[nt][q] = 0.f;

#pragma unroll 4
            for (int ks = 0; ks < 32; ks++) {
                const int kb = ks * 32;
                uint32_t ah[4], al[4];
                ldsm4(ah[0], ah[1], ah[2], ah[3], a_base_hi + kb);
                ldsm4(al[0], al[1], al[2], al[3], a_base_lo + kb);
                uint32_t r0, r1, r2, r3;
                uint32_t bh[2][2], bl[2][2];
                ldsm4(r0, r1, r2, r3, b_base_hi + kb);
                bh[0][0] = r0; bh[0][1] = r1; bh[1][0] = r2; bh[1][1] = r3;
                ldsm4(r0, r1, r2, r3, b_base_lo + kb);
                bl[0][0] = r0; bl[0][1] = r1; bl[1][0] = r2; bl[1][1] = r3;
#pragma unroll
                for (int nt = 0; nt < 2; nt++) {
                    mma16816(df[nt], ah, bh[nt]);
                    mma16816(df[nt], ah, bl[nt]);
                    mma16816(df[nt], al, bh[nt]);
                }
            }

            // ---- write D frags to smem (pitch 34) ----
            {
                int drow = mtw * 16 + (lane >> 2);
                int dcol = ntw * 16 + (lane & 3) * 2;
#pragma unroll
                for (int nt = 0; nt < 2; nt++) {
                    *reinterpret_cast<float2*>(&Dp[drow * 34 + dcol + nt * 8]) =
                        make_float2(df[nt][0], df[nt][1]);
                    *reinterpret_cast<float2*>(&Dp[(drow + 8) * 34 + dcol + nt * 8]) =
                        make_float2(df[nt][2], df[nt][3]);
                }
            }
        }
        __syncthreads();

        // ---- activation + c/h update: 512 (b,uu) pairs over 256 threads ----
#pragma unroll
        for (int p = 0; p < 2; p++) {
            int idx = tid + p * 256;
            int b = idx >> 4;
            int uu = idx & 15;
            size_t xrow = ((size_t)b * NT + tt) * NG + u0 + uu;
            float gi = Dp[(0  + uu) * 34 + b] + xw[xrow];
            float gf = Dp[(16 + uu) * 34 + b] + xw[xrow + 512];
            float gg = Dp[(32 + uu) * 34 + b] + xw[xrow + 1024];
            float go = Dp[(48 + uu) * 34 + b] + xw[xrow + 1536];
            float cprev = Cp[uu * 34 + b];
            float cn = sigf(gf) * cprev + sigf(gi) * tanhf(gg);
            float h  = sigf(go) * tanhf(cn);
            Cp[uu * 34 + b] = cn;
            out[((size_t)b * NT + tt) * (2 * NH) + grp * NH + u0 + uu] = h;
            __nv_bfloat16 hi, lo;
            split_bf16(h, hi, lo);
            hb_hi[b * NH + u0 + uu] = hi;
            hb_lo[b * NH + u0 + uu] = lo;
        }

        // ---- group barrier (release h writes) ----
        __threadfence();
        __syncthreads();
        if (tid == 0) {
            atomicAdd(&g_cnt[grp], 1u);
            while (ld_acq(&g_cnt[grp]) < target) { __nanosleep(64); }
        }
        __syncthreads();
        target += 32u;
    }
}

// ---------------- classifier weight transpose ----------------
__global__ void k_wct(const float* __restrict__ Wc) {
    int i = blockIdx.x * 256 + threadIdx.x;
    if (i < NF * NC) {
        int f = i >> 5, c = i & 31;
        g_WcT[f * NC + c] = Wc[(size_t)c * NF + f];
    }
}

// ---------------- classifier + log-softmax, output (B, C, T) ----------------
__global__ __launch_bounds__(256) void k_cls(const float* __restrict__ truth,
                                             const int* __restrict__ tf,
                                             const float* __restrict__ bc,
                                             float* __restrict__ outp) {
    int warp = threadIdx.x >> 5;
    int lane = threadIdx.x & 31;
    int pos = blockIdx.x * 8 + warp;
    int b = pos >> 9, t = pos & 511;

    float acc = bc[lane];
    float past = 0.f;
    if (tf[0] != 0 && t > 0) past = truth[b * NT + t - 1];
    acc += past * g_WcT[lane];

    const float4* h4 = reinterpret_cast<const float4*>(g_h2 + ((size_t)b * NT + t) * (2 * NH));
    const float* wt = g_WcT + NC;
#pragma unroll 4
    for (int f4 = 0; f4 < 256; f4++) {
        float4 hv = h4[f4];
        int f = f4 * 4;
        acc += hv.x * wt[(f + 0) * NC + lane];
        acc += hv.y * wt[(f + 1) * NC + lane];
        acc += hv.z * wt[(f + 2) * NC + lane];
        acc += hv.w * wt[(f + 3) * NC + lane];
    }

    float m = acc;
#pragma unroll
    for (int o = 16; o > 0; o >>= 1) m = fmaxf(m, __shfl_xor_sync(0xffffffffu, m, o));
    float e = expf(acc - m);
    float s = e;
#pragma unroll
    for (int o = 16; o > 0; o >>= 1) s += __shfl_xor_sync(0xffffffffu, s, o);
    float y = acc - m - logf(s);

    outp[((size_t)b * NC + lane) * NT + t] = y;
}

// ---------------- launch ----------------
extern "C" void kernel_launch(void* const* d_in, const int* in_sizes, int n_in,
                              void* d_out, int out_size) {
    const int*   x     = (const int*)d_in[0];
    const float* truth = (const float*)d_in[1];
    const int*   tf    = (const int*)d_in[2];
    const float* emb   = (const float*)d_in[3];
    const float* Wih0f = (const float*)d_in[4];
    const float* Whh0f = (const float*)d_in[5];
    const float* bih0f = (const float*)d_in[6];
    const float* bhh0f = (const float*)d_in[7];
    const float* Wih0b = (const float*)d_in[8];
    const float* Whh0b = (const float*)d_in[9];
    const float* bih0b = (const float*)d_in[10];
    const float* bhh0b = (const float*)d_in[11];
    const float* Wih1f = (const float*)d_in[12];
    const float* Whh1f = (const float*)d_in[13];
    const float* bih1f = (const float*)d_in[14];
    const float* bhh1f = (const float*)d_in[15];
    const float* Wih1b = (const float*)d_in[16];
    const float* Whh1b = (const float*)d_in[17];
    const float* bih1b = (const float*)d_in[18];
    const float* bhh1b = (const float*)d_in[19];
    const float* Wc    = (const float*)d_in[20];
    const float* bc    = (const float*)d_in[21];

    cudaFuncSetAttribute(k_scan_tc, cudaFuncAttributeMaxDynamicSharedMemorySize, SCAN_SMEM);
    cudaFuncSetAttribute(k_gemm_bf16, cudaFuncAttributeMaxDynamicSharedMemorySize, GSMEM);

    dim3 ggrid(16, 128);
    const int w0_n4 = NG * 512 / 4;
    const int w1_n4 = NG * 1024 / 4;
    const int a1_n4 = NM * 1024 / 4;

    // ---- layer 0 (K = 512) ----
    k_embed<<<NM, 128>>>(x, emb);                                   // -> g_Ahi/g_Alo
    k_init<<<1, 32>>>();
    k_convW<<<(w0_n4 + 255) / 256, 256>>>(Wih0f, w0_n4);
    k_gemm_bf16<<<ggrid, 256, GSMEM>>>(0, bih0f, bhh0f, 512);
    k_convW<<<(w0_n4 + 255) / 256, 256>>>(Wih0b, w0_n4);
    k_gemm_bf16<<<ggrid, 256, GSMEM>>>(1, bih0b, bhh0b, 512);
    k_scan_tc<<<64, 256, SCAN_SMEM>>>(Whh0f, Whh0b, 0);

    // ---- layer 1 (K = 1024) ----
    k_convA<<<(a1_n4 + 255) / 256, 256>>>(a1_n4);                   // g_h1 -> g_Ahi/g_Alo
    k_init<<<1, 32>>>();
    k_convW<<<(w1_n4 + 255) / 256, 256>>>(Wih1f, w1_n4);
    k_gemm_bf16<<<ggrid, 256, GSMEM>>>(0, bih1f, bhh1f, 1024);
    k_convW<<<(w1_n4 + 255) / 256, 256>>>(Wih1b, w1_n4);
    k_gemm_bf16<<<ggrid, 256, GSMEM>>>(1, bih1b, bhh1b, 1024);
    k_scan_tc<<<64, 256, SCAN_SMEM>>>(Whh1f, Whh1b, 1);

    // ---- classifier ----
    k_wct<<<(NF * NC + 255) / 256, 256>>>(Wc);
    k_cls<<<NM / 8, 256>>>(truth, tf, bc, (float*)d_out);

    (void)in_sizes; (void)n_in; (void)out_size;
}

// round 9
// speedup vs baseline: 2.4498x; 1.3106x over previous
#include <cuda_runtime.h>
#include <cuda_bf16.h>
#include <math.h>
#include <stdint.h>

#define NB 32
#define NT 512
#define NE 512
#define NH 512
#define NG 2048      // 4*H
#define NC 32
#define NF 1025      // 2H+1
#define NM (NB * NT) // 16384 rows

// ---------------- static device scratch (allocation-free) ----------------
static __device__ __align__(16) __nv_bfloat16 g_Ahi[(size_t)NM * 1024];
static __device__ __align__(16) __nv_bfloat16 g_Alo[(size_t)NM * 1024];
static __device__ __align__(16) __nv_bfloat16 g_Whi[(size_t)NG * 1024];
static __device__ __align__(16) __nv_bfloat16 g_Wlo[(size_t)NG * 1024];
static __device__ float g_xw_f[(size_t)NM * NG];              // (B,T,4H) fwd
static __device__ float g_xw_b[(size_t)NM * NG];              // (B,T,4H) bwd
static __device__ float g_h1[(size_t)NM * 2 * NH];            // layer0 out
static __device__ float g_h2[(size_t)NM * 2 * NH];            // layer1 out
static __device__ __align__(16) __nv_bfloat16 g_hb_hi[2][2][NB * NH]; // [parity][dir][b*512+u]
static __device__ __align__(16) __nv_bfloat16 g_hb_lo[2][2][NB * NH];
static __device__ float g_WcT[NF * NC];                       // transposed classifier W
static __device__ unsigned g_cnt[2];                          // group barrier counters

// ---------------- helpers ----------------
__device__ __forceinline__ unsigned ld_acq(const unsigned* p) {
    unsigned v;
    asm volatile("ld.acquire.gpu.global.b32 %0, [%1];" : "=r"(v) : "l"(p) : "memory");
    return v;
}
__device__ __forceinline__ float sigf(float x) { return 1.f / (1.f + expf(-x)); }
__device__ __forceinline__ void split_bf16(float v, __nv_bfloat16& hi, __nv_bfloat16& lo) {
    hi = __float2bfloat16(v);
    lo = __float2bfloat16(v - __bfloat162float(hi));
}
__device__ __forceinline__ uint32_t smem_to_u32(const void* p) {
    uint32_t a;
    asm("{ .reg .u64 t; cvta.to.shared.u64 t, %1; cvt.u32.u64 %0, t; }" : "=r"(a) : "l"(p));
    return a;
}
__device__ __forceinline__ void cp_async16(uint32_t sa, const void* ga) {
    asm volatile("cp.async.cg.shared.global [%0], [%1], 16;" :: "r"(sa), "l"(ga));
}
__device__ __forceinline__ void ldsm4(uint32_t& r0, uint32_t& r1, uint32_t& r2, uint32_t& r3,
                                      uint32_t addr) {
    asm volatile("ldmatrix.sync.aligned.m8n8.x4.shared.b16 {%0,%1,%2,%3}, [%4];"
                 : "=r"(r0), "=r"(r1), "=r"(r2), "=r"(r3) : "r"(addr));
}
__device__ __forceinline__ void mma16816(float* d, const uint32_t* a, const uint32_t* b) {
    asm volatile(
        "mma.sync.aligned.m16n8k16.row.col.f32.bf16.bf16.f32 "
        "{%0,%1,%2,%3}, {%4,%5,%6,%7}, {%8,%9}, {%0,%1,%2,%3};"
        : "+f"(d[0]), "+f"(d[1]), "+f"(d[2]), "+f"(d[3])
        : "r"(a[0]), "r"(a[1]), "r"(a[2]), "r"(a[3]), "r"(b[0]), "r"(b[1]));
}

// ---------------- embedding gather -> bf16 hi/lo (K=512) ----------------
__global__ void k_embed(const int* __restrict__ x, const float* __restrict__ emb) {
    int bt = blockIdx.x;
    int e4 = threadIdx.x;            // 0..127
    int row = x[bt];
    float4 v = reinterpret_cast<const float4*>(emb)[(size_t)row * 128 + e4];
    __nv_bfloat16 hi[4], lo[4];
    split_bf16(v.x, hi[0], lo[0]); split_bf16(v.y, hi[1], lo[1]);
    split_bf16(v.z, hi[2], lo[2]); split_bf16(v.w, hi[3], lo[3]);
    size_t o = (size_t)bt * 128 + e4;   // uint2 index
    reinterpret_cast<uint2*>(g_Ahi)[o] = *reinterpret_cast<uint2*>(hi);
    reinterpret_cast<uint2*>(g_Alo)[o] = *reinterpret_cast<uint2*>(lo);
}

// ---------------- weight fp32 -> bf16 hi/lo ----------------
__global__ void k_convW(const float* __restrict__ src, int n4) {
    int i = blockIdx.x * 256 + threadIdx.x;
    if (i >= n4) return;
    float4 v = reinterpret_cast<const float4*>(src)[i];
    __nv_bfloat16 hi[4], lo[4];
    split_bf16(v.x, hi[0], lo[0]); split_bf16(v.y, hi[1], lo[1]);
    split_bf16(v.z, hi[2], lo[2]); split_bf16(v.w, hi[3], lo[3]);
    reinterpret_cast<uint2*>(g_Whi)[i] = *reinterpret_cast<uint2*>(hi);
    reinterpret_cast<uint2*>(g_Wlo)[i] = *reinterpret_cast<uint2*>(lo);
}

// ---------------- HMMA input GEMM (unchanged from passing R5/R6) ----------------
#define SKP 40
#define TILE_B (128 * SKP * 2)       // 10240 B per tile
#define BUF_B (4 * TILE_B)           // 40960 B per stage
#define GSMEM (2 * BUF_B)            // 81920 B

__global__ __launch_bounds__(256, 1) void k_gemm_bf16(int dst_mode,
                                                      const float* __restrict__ b1,
                                                      const float* __restrict__ b2,
                                                      int K) {
    extern __shared__ __align__(16) char smem[];
    uint32_t sb = smem_to_u32(smem);
    float* __restrict__ C = dst_mode ? g_xw_b : g_xw_f;

    const int tid = threadIdx.x;
    const int lane = tid & 31;
    const int wid = tid >> 5;
    const int wm = wid & 3;
    const int wn = wid >> 2;
    const int n0 = blockIdx.x * 128;
    const int m0 = blockIdx.y * 128;

    float d[2][8][4];
#pragma unroll
    for (int mt = 0; mt < 2; mt++)
#pragma unroll
        for (int nt = 0; nt < 8; nt++)
#pragma unroll
            for (int q = 0; q < 4; q++) d[mt][nt][q] = 0.f;

    auto load_chunk = [&](int ch, int buf) {
        const int k0 = ch << 5;
        const uint32_t sbb = sb + buf * BUF_B;
#pragma unroll
        for (int tile = 0; tile < 4; tile++) {
            const __nv_bfloat16* gsrc =
                tile == 0 ? g_Ahi : tile == 1 ? g_Alo : tile == 2 ? g_Whi : g_Wlo;
            const int base = tile < 2 ? m0 : n0;
#pragma unroll
            for (int half = 0; half < 2; half++) {
                int idx = half * 256 + tid;
                int r = idx >> 2, s = idx & 3;
                const void* ga = gsrc + (size_t)(base + r) * K + k0 + s * 8;
                cp_async16(sbb + tile * TILE_B + r * (SKP * 2) + s * 16, ga);
            }
        }
        asm volatile("cp.async.commit_group;" ::: "memory");
    };

    const int nch = K >> 5;
    load_chunk(0, 0);

    for (int ch = 0; ch < nch; ch++) {
        if (ch + 1 < nch) {
            load_chunk(ch + 1, (ch + 1) & 1);
            asm volatile("cp.async.wait_group 1;" ::: "memory");
        } else {
            asm volatile("cp.async.wait_group 0;" ::: "memory");
        }
        __syncthreads();

        const uint32_t Ah = sb + (ch & 1) * BUF_B;
        const uint32_t Wh = Ah + 2 * TILE_B;

#pragma unroll
        for (int k16 = 0; k16 < 2; k16++) {
            const int kb = k16 * 32;

            uint32_t ahi[2][4], alo[2][4];
#pragma unroll
            for (int mt = 0; mt < 2; mt++) {
                uint32_t addr = Ah + (wm * 32 + mt * 16 + (lane & 15)) * (SKP * 2)
                                + ((lane >> 4) << 4) + kb;
                ldsm4(ahi[mt][0], ahi[mt][1], ahi[mt][2], ahi[mt][3], addr);
                ldsm4(alo[mt][0], alo[mt][1], alo[mt][2], alo[mt][3], addr + TILE_B);
            }

            uint32_t bhi[8][2], blo[8][2];
#pragma unroll
            for (int j = 0; j < 4; j++) {
                uint32_t addr = Wh + (wn * 64 + j * 16 + (lane & 7) + ((lane >> 4) << 3)) * (SKP * 2)
                                + (((lane >> 3) & 1) << 4) + kb;
                uint32_t r0, r1, r2, r3;
                ldsm4(r0, r1, r2, r3, addr);
                bhi[2 * j][0] = r0; bhi[2 * j][1] = r1;
                bhi[2 * j + 1][0] = r2; bhi[2 * j + 1][1] = r3;
                ldsm4(r0, r1, r2, r3, addr + TILE_B);
                blo[2 * j][0] = r0; blo[2 * j][1] = r1;
                blo[2 * j + 1][0] = r2; blo[2 * j + 1][1] = r3;
            }

#pragma unroll
            for (int mt = 0; mt < 2; mt++)
#pragma unroll
                for (int nt = 0; nt < 8; nt++) {
                    mma16816(d[mt][nt], ahi[mt], bhi[nt]);
                    mma16816(d[mt][nt], ahi[mt], blo[nt]);
                    mma16816(d[mt][nt], alo[mt], bhi[nt]);
                }
        }
        __syncthreads();
    }

#pragma unroll
    for (int nt = 0; nt < 8; nt++) {
        int n = n0 + wn * 64 + nt * 8 + 2 * (lane & 3);
        float bx = b1[n] + b2[n];
        float by = b1[n + 1] + b2[n + 1];
#pragma unroll
        for (int mt = 0; mt < 2; mt++) {
            int m = m0 + wm * 32 + mt * 16 + (lane >> 2);
            float2 v0 = make_float2(d[mt][nt][0] + bx, d[mt][nt][1] + by);
            float2 v1 = make_float2(d[mt][nt][2] + bx, d[mt][nt][3] + by);
            *reinterpret_cast<float2*>(&C[(size_t)m * NG + n]) = v0;
            *reinterpret_cast<float2*>(&C[(size_t)(m + 8) * NG + n]) = v1;
        }
    }
}

// ---------------- barrier counter init ----------------
__global__ void k_init() {
    if (threadIdx.x < 2) g_cnt[threadIdx.x] = 0u;
}

// ---------------- tensor-core recurrent scan (128 blocks, 8 units each) ----------------
// Blocks 0..63 fwd, 64..127 bwd. Each block owns 8 hidden units = 32 gate rows.
// Per step: D(32x32) = WhhSlice(32x512) . h^T, bf16 hi/lo 3-term HMMA.
// 8 warps = (mtw 2) x (ntw 2, n16 each) x (kh 2, K halves -> two partial-D buffers).
// Layer 0 additionally writes bf16 hi/lo h into g_Ahi/g_Alo (fused convA).
#define SPITCH 1040                          // 520 bf16/row (conflict-free ldmatrix)
#define OFF_AHI 0
#define OFF_ALO (OFF_AHI + 32 * SPITCH)      // 33280
#define OFF_BHI (OFF_ALO + 32 * SPITCH)      // 66560
#define OFF_BLO (OFF_BHI + 32 * SPITCH)      // 99840
#define OFF_D0  (OFF_BLO + 32 * SPITCH)      // 133120  (32 x 36 fp32)
#define OFF_D1  (OFF_D0 + 32 * 36 * 4)       // 137728
#define SCAN_SMEM (OFF_D1 + 32 * 36 * 4)     // 142336

__global__ __launch_bounds__(256, 1) void k_scan_tc(const float* __restrict__ Whh_f,
                                                    const float* __restrict__ Whh_b,
                                                    int layer) {
    extern __shared__ __align__(16) char smem[];
    const uint32_t sb = smem_to_u32(smem);
    float* const D0 = reinterpret_cast<float*>(smem + OFF_D0);
    float* const D1 = reinterpret_cast<float*>(smem + OFF_D1);

    const int tid = threadIdx.x;
    const int lane = tid & 31;
    const int wid = tid >> 5;
    const int kh  = wid & 1;          // K half
    const int ntw = (wid >> 1) & 1;   // n16 tile
    const int mtw = wid >> 2;         // m16 tile (0..1)
    const int grp = blockIdx.x >> 6;  // 0 fwd, 1 bwd
    const int ub  = blockIdx.x & 63;
    const int u0  = ub * 8;           // first owned hidden unit

    const float* __restrict__ xw  = grp ? g_xw_b : g_xw_f;
    const float* __restrict__ Whh = grp ? Whh_b : Whh_f;
    float* __restrict__ out       = layer ? g_h2 : g_h1;
    __nv_bfloat16* const hb_hi0 = g_hb_hi[0][grp];
    __nv_bfloat16* const hb_lo0 = g_hb_lo[0][grp];
    __nv_bfloat16* const hb_hi1 = g_hb_hi[1][grp];
    __nv_bfloat16* const hb_lo1 = g_hb_lo[1][grp];

    // ---- init: Whh slice (32 rows x 512) -> smem bf16 hi/lo ----
    {
        int m = tid >> 3;                 // 0..31 slice row (gate*8 + unit)
        int kq = (tid & 7) * 64;          // 64-float span
        int gcol = ((m >> 3) << 9) + u0 + (m & 7);
        const float4* wp = reinterpret_cast<const float4*>(Whh + (size_t)gcol * NH + kq);
        char* arow_hi = smem + OFF_AHI + m * SPITCH + kq * 2;
        char* arow_lo = smem + OFF_ALO + m * SPITCH + kq * 2;
#pragma unroll
        for (int i = 0; i < 16; i++) {
            float4 v = wp[i];
            __nv_bfloat16 hi[4], lo[4];
            split_bf16(v.x, hi[0], lo[0]); split_bf16(v.y, hi[1], lo[1]);
            split_bf16(v.z, hi[2], lo[2]); split_bf16(v.w, hi[3], lo[3]);
            *reinterpret_cast<uint2*>(arow_hi + i * 8) = *reinterpret_cast<uint2*>(hi);
            *reinterpret_cast<uint2*>(arow_lo + i * 8) = *reinterpret_cast<uint2*>(lo);
        }
    }
    __syncthreads();

    // ldmatrix base addresses (R5/R6 hardware-proven mappings; pitch = SPITCH)
    const uint32_t a_base_hi = sb + OFF_AHI + (mtw * 16 + (lane & 15)) * SPITCH + ((lane >> 4) << 4);
    const uint32_t a_base_lo = a_base_hi + (OFF_ALO - OFF_AHI);
    const uint32_t b_base_hi = sb + OFF_BHI
        + (ntw * 16 + (lane & 7) + ((lane >> 4) << 3)) * SPITCH + (((lane >> 3) & 1) << 4);
    const uint32_t b_base_lo = b_base_hi + (OFF_BLO - OFF_BHI);
    const int kh_off = kh * 512;           // byte offset of this warp's K half

    // activation binding: thread <-> (batch, unit), loop-invariant
    const int ab = tid >> 3;          // batch 0..31
    const int auu = tid & 7;          // unit 0..7
    float c_reg = 0.f;

    unsigned target = 64u;
    for (int t = 0; t < NT; t++) {
        const int tt = grp ? (NT - 1 - t) : t;

        // ---- prefetch this step's input-GEMM gate values (independent of h) ----
        const size_t xrow = ((size_t)ab * NT + tt) * NG + u0 + auu;
        float xwp0 = __ldcg(xw + xrow);
        float xwp1 = __ldcg(xw + xrow + 512);
        float xwp2 = __ldcg(xw + xrow + 1024);
        float xwp3 = __ldcg(xw + xrow + 1536);

        if (t > 0) {
            const __nv_bfloat16* hb_hi = ((t - 1) & 1) ? hb_hi1 : hb_hi0;
            const __nv_bfloat16* hb_lo = ((t - 1) & 1) ? hb_lo1 : hb_lo0;
            // ---- stage h (32 x 512 bf16 hi/lo) global -> smem ----
#pragma unroll
            for (int i = 0; i < 8; i++) {
                int idx = i * 256 + tid;          // 0..2047
                int b = idx >> 6, c = idx & 63;
                uint4 vhi = __ldcg(reinterpret_cast<const uint4*>(hb_hi + b * NH + c * 8));
                uint4 vlo = __ldcg(reinterpret_cast<const uint4*>(hb_lo + b * NH + c * 8));
                *reinterpret_cast<uint4*>(smem + OFF_BHI + b * SPITCH + c * 16) = vhi;
                *reinterpret_cast<uint4*>(smem + OFF_BLO + b * SPITCH + c * 16) = vlo;
            }
            __syncthreads();

            // ---- HMMA: partial D(32x32) over this warp's K half ----
            float df[2][4];
#pragma unroll
            for (int nt = 0; nt < 2; nt++)
#pragma unroll
                for (int q = 0; q < 4; q++) df[nt][q] = 0.f;

#pragma unroll 4
            for (int ks = 0; ks < 16; ks++) {
                const int kb = kh_off + ks * 32;
                uint32_t ah[4], al[4];
                ldsm4(ah[0], ah[1], ah[2], ah[3], a_base_hi + kb);
                ldsm4(al[0], al[1], al[2], al[3], a_base_lo + kb);
                uint32_t r0, r1, r2, r3;
                uint32_t bh[2][2], bl[2][2];
                ldsm4(r0, r1, r2, r3, b_base_hi + kb);
                bh[0][0] = r0; bh[0][1] = r1; bh[1][0] = r2; bh[1][1] = r3;
                ldsm4(r0, r1, r2, r3, b_base_lo + kb);
                bl[0][0] = r0; bl[0][1] = r1; bl[1][0] = r2; bl[1][1] = r3;
#pragma unroll
                for (int nt = 0; nt < 2; nt++) {
                    mma16816(df[nt], ah, bh[nt]);
                    mma16816(df[nt], ah, bl[nt]);
                    mma16816(df[nt], al, bh[nt]);
                }
            }

            // ---- write partial D frags (pitch 36) ----
            {
                float* Dp = kh ? D1 : D0;
                int drow = mtw * 16 + (lane >> 2);
                int dcol = ntw * 16 + (lane & 3) * 2;
#pragma unroll
                for (int nt = 0; nt < 2; nt++) {
                    *reinterpret_cast<float2*>(&Dp[drow * 36 + dcol + nt * 8]) =
                        make_float2(df[nt][0], df[nt][1]);
                    *reinterpret_cast<float2*>(&Dp[(drow + 8) * 36 + dcol + nt * 8]) =
                        make_float2(df[nt][2], df[nt][3]);
                }
            }
        }
        __syncthreads();

        // ---- activation + c/h update (one (b,uu) pair per thread) ----
        {
            float gi = xwp0, gf = xwp1, gg = xwp2, go = xwp3;
            if (t > 0) {
                gi += D0[(0  + auu) * 36 + ab] + D1[(0  + auu) * 36 + ab];
                gf += D0[(8  + auu) * 36 + ab] + D1[(8  + auu) * 36 + ab];
                gg += D0[(16 + auu) * 36 + ab] + D1[(16 + auu) * 36 + ab];
                go += D0[(24 + auu) * 36 + ab] + D1[(24 + auu) * 36 + ab];
            }
            float cn = sigf(gf) * c_reg + sigf(gi) * tanhf(gg);
            float h  = sigf(go) * tanhf(cn);
            c_reg = cn;
            out[((size_t)ab * NT + tt) * (2 * NH) + grp * NH + u0 + auu] = h;
            __nv_bfloat16 hi, lo;
            split_bf16(h, hi, lo);
            if (t & 1) {
                hb_hi1[ab * NH + u0 + auu] = hi;
                hb_lo1[ab * NH + u0 + auu] = lo;
            } else {
                hb_hi0[ab * NH + u0 + auu] = hi;
                hb_lo0[ab * NH + u0 + auu] = lo;
            }
            if (layer == 0) {
                // fused convA: layer-1 GEMM A operand, row = b*NT+tt, col = grp*512+u
                size_t aidx = ((size_t)ab * NT + tt) * 1024 + grp * NH + u0 + auu;
                g_Ahi[aidx] = hi;
                g_Alo[aidx] = lo;
            }
        }

        // ---- group barrier (release h writes) ----
        __threadfence();
        __syncthreads();
        if (tid == 0) {
            atomicAdd(&g_cnt[grp], 1u);
            while (ld_acq(&g_cnt[grp]) < target) { __nanosleep(64); }
        }
        __syncthreads();
        target += 64u;
    }
}

// ---------------- classifier weight transpose ----------------
__global__ void k_wct(const float* __restrict__ Wc) {
    int i = blockIdx.x * 256 + threadIdx.x;
    if (i < NF * NC) {
        int f = i >> 5, c = i & 31;
        g_WcT[f * NC + c] = Wc[(size_t)c * NF + f];
    }
}

// ---------------- classifier + log-softmax, output (B, C, T) ----------------
__global__ __launch_bounds__(256) void k_cls(const float* __restrict__ truth,
                                             const int* __restrict__ tf,
                                             const float* __restrict__ bc,
                                             float* __restrict__ outp) {
    int warp = threadIdx.x >> 5;
    int lane = threadIdx.x & 31;
    int pos = blockIdx.x * 8 + warp;
    int b = pos >> 9, t = pos & 511;

    float acc = bc[lane];
    float past = 0.f;
    if (tf[0] != 0 && t > 0) past = truth[b * NT + t - 1];
    acc += past * g_WcT[lane];

    const float4* h4 = reinterpret_cast<const float4*>(g_h2 + ((size_t)b * NT + t) * (2 * NH));
    const float* wt = g_WcT + NC;
#pragma unroll 4
    for (int f4 = 0; f4 < 256; f4++) {
        float4 hv = h4[f4];
        int f = f4 * 4;
        acc += hv.x * wt[(f + 0) * NC + lane];
        acc += hv.y * wt[(f + 1) * NC + lane];
        acc += hv.z * wt[(f + 2) * NC + lane];
        acc += hv.w * wt[(f + 3) * NC + lane];
    }

    float m = acc;
#pragma unroll
    for (int o = 16; o > 0; o >>= 1) m = fmaxf(m, __shfl_xor_sync(0xffffffffu, m, o));
    float e = expf(acc - m);
    float s = e;
#pragma unroll
    for (int o = 16; o > 0; o >>= 1) s += __shfl_xor_sync(0xffffffffu, s, o);
    float y = acc - m - logf(s);

    outp[((size_t)b * NC + lane) * NT + t] = y;
}

// ---------------- launch ----------------
extern "C" void kernel_launch(void* const* d_in, const int* in_sizes, int n_in,
                              void* d_out, int out_size) {
    const int*   x     = (const int*)d_in[0];
    const float* truth = (const float*)d_in[1];
    const int*   tf    = (const int*)d_in[2];
    const float* emb   = (const float*)d_in[3];
    const float* Wih0f = (const float*)d_in[4];
    const float* Whh0f = (const float*)d_in[5];
    const float* bih0f = (const float*)d_in[6];
    const float* bhh0f = (const float*)d_in[7];
    const float* Wih0b = (const float*)d_in[8];
    const float* Whh0b = (const float*)d_in[9];
    const float* bih0b = (const float*)d_in[10];
    const float* bhh0b = (const float*)d_in[11];
    const float* Wih1f = (const float*)d_in[12];
    const float* Whh1f = (const float*)d_in[13];
    const float* bih1f = (const float*)d_in[14];
    const float* bhh1f = (const float*)d_in[15];
    const float* Wih1b = (const float*)d_in[16];
    const float* Whh1b = (const float*)d_in[17];
    const float* bih1b = (const float*)d_in[18];
    const float* bhh1b = (const float*)d_in[19];
    const float* Wc    = (const float*)d_in[20];
    const float* bc    = (const float*)d_in[21];

    cudaFuncSetAttribute(k_scan_tc, cudaFuncAttributeMaxDynamicSharedMemorySize, SCAN_SMEM);
    cudaFuncSetAttribute(k_gemm_bf16, cudaFuncAttributeMaxDynamicSharedMemorySize, GSMEM);

    dim3 ggrid(16, 128);
    const int w0_n4 = NG * 512 / 4;
    const int w1_n4 = NG * 1024 / 4;

    // ---- layer 0 (K = 512) ----
    k_embed<<<NM, 128>>>(x, emb);                                   // -> g_Ahi/g_Alo
    k_init<<<1, 32>>>();
    k_convW<<<(w0_n4 + 255) / 256, 256>>>(Wih0f, w0_n4);
    k_gemm_bf16<<<ggrid, 256, GSMEM>>>(0, bih0f, bhh0f, 512);
    k_convW<<<(w0_n4 + 255) / 256, 256>>>(Wih0b, w0_n4);
    k_gemm_bf16<<<ggrid, 256, GSMEM>>>(1, bih0b, bhh0b, 512);
    k_scan_tc<<<128, 256, SCAN_SMEM>>>(Whh0f, Whh0b, 0);            // also fills g_Ahi/g_Alo

    // ---- layer 1 (K = 1024) ----
    k_init<<<1, 32>>>();
    k_convW<<<(w1_n4 + 255) / 256, 256>>>(Wih1f, w1_n4);
    k_gemm_bf16<<<ggrid, 256, GSMEM>>>(0, bih1f, bhh1f, 1024);
    k_convW<<<(w1_n4 + 255) / 256, 256>>>(Wih1b, w1_n4);
    k_gemm_bf16<<<ggrid, 256, GSMEM>>>(1, bih1b, bhh1b, 1024);
    k_scan_tc<<<128, 256, SCAN_SMEM>>>(Whh1f, Whh1b, 1);

    // ---- classifier ----
    k_wct<<<(NF * NC + 255) / 256, 256>>>(Wc);
    k_cls<<<NM / 8, 256>>>(truth, tf, bc, (float*)d_out);

    (void)in_sizes; (void)n_in; (void)out_size;
}

// round 12
// speedup vs baseline: 2.7066x; 1.1048x over previous
#include <cuda_runtime.h>
#include <cuda_bf16.h>
#include <math.h>
#include <stdint.h>

#define NB 32
#define NT 512
#define NE 512
#define NH 512
#define NG 2048      // 4*H
#define NC 32
#define NF 1025      // 2H+1
#define NM (NB * NT) // 16384 rows

// ---------------- static device scratch (allocation-free) ----------------
static __device__ __align__(16) __nv_bfloat16 g_Ahi[(size_t)NM * 1024];
static __device__ __align__(16) __nv_bfloat16 g_Alo[(size_t)NM * 1024];
static __device__ __align__(16) __nv_bfloat16 g_Whi[(size_t)NG * 1024];
static __device__ __align__(16) __nv_bfloat16 g_Wlo[(size_t)NG * 1024];
static __device__ float g_xw_f[(size_t)NM * NG];              // (B,T,4H) fwd
static __device__ float g_xw_b[(size_t)NM * NG];              // (B,T,4H) bwd
static __device__ float g_h1[(size_t)NM * 2 * NH];            // layer0 out
static __device__ float g_h2[(size_t)NM * 2 * NH];            // layer1 out
static __device__ __align__(16) __nv_bfloat16 g_hb_hi[2][2][NB * NH]; // [parity][dir][b*512+u]
static __device__ __align__(16) __nv_bfloat16 g_hb_lo[2][2][NB * NH];
static __device__ float g_WcT[NF * NC];                       // transposed classifier W
static __device__ unsigned g_cnt[2];                          // group barrier counters

// ---------------- helpers ----------------
__device__ __forceinline__ unsigned ld_acq(const unsigned* p) {
    unsigned v;
    asm volatile("ld.acquire.gpu.global.b32 %0, [%1];" : "=r"(v) : "l"(p) : "memory");
    return v;
}
__device__ __forceinline__ float sigf(float x) { return 1.f / (1.f + expf(-x)); }
__device__ __forceinline__ void split_bf16(float v, __nv_bfloat16& hi, __nv_bfloat16& lo) {
    hi = __float2bfloat16(v);
    lo = __float2bfloat16(v - __bfloat162float(hi));
}
__device__ __forceinline__ uint32_t smem_to_u32(const void* p) {
    uint32_t a;
    asm("{ .reg .u64 t; cvta.to.shared.u64 t, %1; cvt.u32.u64 %0, t; }" : "=r"(a) : "l"(p));
    return a;
}
__device__ __forceinline__ void cp_async16(uint32_t sa, const void* ga) {
    asm volatile("cp.async.cg.shared.global [%0], [%1], 16;" :: "r"(sa), "l"(ga));
}
__device__ __forceinline__ void ldsm4(uint32_t& r0, uint32_t& r1, uint32_t& r2, uint32_t& r3,
                                      uint32_t addr) {
    asm volatile("ldmatrix.sync.aligned.m8n8.x4.shared.b16 {%0,%1,%2,%3}, [%4];"
                 : "=r"(r0), "=r"(r1), "=r"(r2), "=r"(r3) : "r"(addr));
}
__device__ __forceinline__ void mma16816(float* d, const uint32_t* a, const uint32_t* b) {
    asm volatile(
        "mma.sync.aligned.m16n8k16.row.col.f32.bf16.bf16.f32 "
        "{%0,%1,%2,%3}, {%4,%5,%6,%7}, {%8,%9}, {%0,%1,%2,%3};"
        : "+f"(d[0]), "+f"(d[1]), "+f"(d[2]), "+f"(d[3])
        : "r"(a[0]), "r"(a[1]), "r"(a[2]), "r"(a[3]), "r"(b[0]), "r"(b[1]));
}

// ---------------- embedding gather -> bf16 hi/lo (K=512) ----------------
__global__ void k_embed(const int* __restrict__ x, const float* __restrict__ emb) {
    int bt = blockIdx.x;
    int e4 = threadIdx.x;            // 0..127
    int row = x[bt];
    float4 v = reinterpret_cast<const float4*>(emb)[(size_t)row * 128 + e4];
    __nv_bfloat16 hi[4], lo[4];
    split_bf16(v.x, hi[0], lo[0]); split_bf16(v.y, hi[1], lo[1]);
    split_bf16(v.z, hi[2], lo[2]); split_bf16(v.w, hi[3], lo[3]);
    size_t o = (size_t)bt * 128 + e4;   // uint2 index
    reinterpret_cast<uint2*>(g_Ahi)[o] = *reinterpret_cast<uint2*>(hi);
    reinterpret_cast<uint2*>(g_Alo)[o] = *reinterpret_cast<uint2*>(lo);
}

// ---------------- weight fp32 -> bf16 hi/lo ----------------
__global__ void k_convW(const float* __restrict__ src, int n4) {
    int i = blockIdx.x * 256 + threadIdx.x;
    if (i >= n4) return;
    float4 v = reinterpret_cast<const float4*>(src)[i];
    __nv_bfloat16 hi[4], lo[4];
    split_bf16(v.x, hi[0], lo[0]); split_bf16(v.y, hi[1], lo[1]);
    split_bf16(v.z, hi[2], lo[2]); split_bf16(v.w, hi[3], lo[3]);
    reinterpret_cast<uint2*>(g_Whi)[i] = *reinterpret_cast<uint2*>(hi);
    reinterpret_cast<uint2*>(g_Wlo)[i] = *reinterpret_cast<uint2*>(lo);
}

// ---------------- HMMA input GEMM (R5-proven; 2 CTAs/SM) ----------------
#define SKP 40
#define TILE_B (128 * SKP * 2)       // 10240 B per tile
#define BUF_B (4 * TILE_B)           // 40960 B per stage
#define GSMEM (2 * BUF_B)            // 81920 B

__global__ __launch_bounds__(256, 2) void k_gemm_bf16(int dst_mode,
                                                      const float* __restrict__ b1,
                                                      const float* __restrict__ b2,
                                                      int K) {
    extern __shared__ __align__(16) char smem[];
    uint32_t sb = smem_to_u32(smem);
    float* __restrict__ C = dst_mode ? g_xw_b : g_xw_f;

    const int tid = threadIdx.x;
    const int lane = tid & 31;
    const int wid = tid >> 5;
    const int wm = wid & 3;
    const int wn = wid >> 2;
    const int n0 = blockIdx.x * 128;
    const int m0 = blockIdx.y * 128;

    float d[2][8][4];
#pragma unroll
    for (int mt = 0; mt < 2; mt++)
#pragma unroll
        for (int nt = 0; nt < 8; nt++)
#pragma unroll
            for (int q = 0; q < 4; q++) d[mt][nt][q] = 0.f;

    auto load_chunk = [&](int ch, int buf) {
        const int k0 = ch << 5;
        const uint32_t sbb = sb + buf * BUF_B;
#pragma unroll
        for (int tile = 0; tile < 4; tile++) {
            const __nv_bfloat16* gsrc =
                tile == 0 ? g_Ahi : tile == 1 ? g_Alo : tile == 2 ? g_Whi : g_Wlo;
            const int base = tile < 2 ? m0 : n0;
#pragma unroll
            for (int half = 0; half < 2; half++) {
                int idx = half * 256 + tid;
                int r = idx >> 2, s = idx & 3;
                const void* ga = gsrc + (size_t)(base + r) * K + k0 + s * 8;
                cp_async16(sbb + tile * TILE_B + r * (SKP * 2) + s * 16, ga);
            }
        }
        asm volatile("cp.async.commit_group;" ::: "memory");
    };

    const int nch = K >> 5;
    load_chunk(0, 0);

    for (int ch = 0; ch < nch; ch++) {
        if (ch + 1 < nch) {
            load_chunk(ch + 1, (ch + 1) & 1);
            asm volatile("cp.async.wait_group 1;" ::: "memory");
        } else {
            asm volatile("cp.async.wait_group 0;" ::: "memory");
        }
        __syncthreads();

        const uint32_t Ah = sb + (ch & 1) * BUF_B;
        const uint32_t Wh = Ah + 2 * TILE_B;

#pragma unroll
        for (int k16 = 0; k16 < 2; k16++) {
            const int kb = k16 * 32;

            uint32_t ahi[2][4], alo[2][4];
#pragma unroll
            for (int mt = 0; mt < 2; mt++) {
                uint32_t addr = Ah + (wm * 32 + mt * 16 + (lane & 15)) * (SKP * 2)
                                + ((lane >> 4) << 4) + kb;
                ldsm4(ahi[mt][0], ahi[mt][1], ahi[mt][2], ahi[mt][3], addr);
                ldsm4(alo[mt][0], alo[mt][1], alo[mt][2], alo[mt][3], addr + TILE_B);
            }

            uint32_t bhi[8][2], blo[8][2];
#pragma unroll
            for (int j = 0; j < 4; j++) {
                uint32_t addr = Wh + (wn * 64 + j * 16 + (lane & 7) + ((lane >> 4) << 3)) * (SKP * 2)
                                + (((lane >> 3) & 1) << 4) + kb;
                uint32_t r0, r1, r2, r3;
                ldsm4(r0, r1, r2, r3, addr);
                bhi[2 * j][0] = r0; bhi[2 * j][1] = r1;
                bhi[2 * j + 1][0] = r2; bhi[2 * j + 1][1] = r3;
                ldsm4(r0, r1, r2, r3, addr + TILE_B);
                blo[2 * j][0] = r0; blo[2 * j][1] = r1;
                blo[2 * j + 1][0] = r2; blo[2 * j + 1][1] = r3;
            }

#pragma unroll
            for (int mt = 0; mt < 2; mt++)
#pragma unroll
                for (int nt = 0; nt < 8; nt++) {
                    mma16816(d[mt][nt], ahi[mt], bhi[nt]);
                    mma16816(d[mt][nt], ahi[mt], blo[nt]);
                    mma16816(d[mt][nt], alo[mt], bhi[nt]);
                }
        }
        __syncthreads();
    }

#pragma unroll
    for (int nt = 0; nt < 8; nt++) {
        int n = n0 + wn * 64 + nt * 8 + 2 * (lane & 3);
        float bx = b1[n] + b2[n];
        float by = b1[n + 1] + b2[n + 1];
#pragma unroll
        for (int mt = 0; mt < 2; mt++) {
            int m = m0 + wm * 32 + mt * 16 + (lane >> 2);
            float2 v0 = make_float2(d[mt][nt][0] + bx, d[mt][nt][1] + by);
            float2 v1 = make_float2(d[mt][nt][2] + bx, d[mt][nt][3] + by);
            *reinterpret_cast<float2*>(&C[(size_t)m * NG + n]) = v0;
            *reinterpret_cast<float2*>(&C[(size_t)(m + 8) * NG + n]) = v1;
        }
    }
}

// ---------------- barrier counter init ----------------
__global__ void k_init() {
    if (threadIdx.x < 2) g_cnt[threadIdx.x] = 0u;
}

// ---------------- tensor-core recurrent scan (128 blocks, 8 units each) ----------------
// Blocks 0..63 fwd, 64..127 bwd. Each block owns 8 hidden units = 32 gate rows.
// Per step: D(32x32) = WhhSlice(32x512) . h^T, bf16 hi/lo 3-term HMMA.
// 8 warps = (mtw 2) x (ntw 2, n16 each) x (kh 2, K halves -> two partial-D buffers).
// Layer 0 additionally writes bf16 hi/lo h into g_Ahi/g_Alo (fused convA).
// xw gate loads for step t+1 issued behind the barrier spin (latency hidden).
#define SPITCH 1040                          // 520 bf16/row (conflict-free ldmatrix)
#define OFF_AHI 0
#define OFF_ALO (OFF_AHI + 32 * SPITCH)      // 33280
#define OFF_BHI (OFF_ALO + 32 * SPITCH)      // 66560
#define OFF_BLO (OFF_BHI + 32 * SPITCH)      // 99840
#define OFF_D0  (OFF_BLO + 32 * SPITCH)      // 133120  (32 x 36 fp32)
#define OFF_D1  (OFF_D0 + 32 * 36 * 4)       // 137728
#define SCAN_SMEM (OFF_D1 + 32 * 36 * 4)     // 142336

__global__ __launch_bounds__(256, 1) void k_scan_tc(const float* __restrict__ Whh_f,
                                                    const float* __restrict__ Whh_b,
                                                    int layer) {
    extern __shared__ __align__(16) char smem[];
    const uint32_t sb = smem_to_u32(smem);
    float* const D0 = reinterpret_cast<float*>(smem + OFF_D0);
    float* const D1 = reinterpret_cast<float*>(smem + OFF_D1);

    const int tid = threadIdx.x;
    const int lane = tid & 31;
    const int wid = tid >> 5;
    const int kh  = wid & 1;          // K half
    const int ntw = (wid >> 1) & 1;   // n16 tile
    const int mtw = wid >> 2;         // m16 tile (0..1)
    const int grp = blockIdx.x >> 6;  // 0 fwd, 1 bwd
    const int ub  = blockIdx.x & 63;
    const int u0  = ub * 8;           // first owned hidden unit

    const float* __restrict__ xw  = grp ? g_xw_b : g_xw_f;
    const float* __restrict__ Whh = grp ? Whh_b : Whh_f;
    float* __restrict__ out       = layer ? g_h2 : g_h1;
    __nv_bfloat16* const hb_hi0 = g_hb_hi[0][grp];
    __nv_bfloat16* const hb_lo0 = g_hb_lo[0][grp];
    __nv_bfloat16* const hb_hi1 = g_hb_hi[1][grp];
    __nv_bfloat16* const hb_lo1 = g_hb_lo[1][grp];

    // ---- init: Whh slice (32 rows x 512) -> smem bf16 hi/lo ----
    {
        int m = tid >> 3;                 // 0..31 slice row (gate*8 + unit)
        int kq = (tid & 7) * 64;          // 64-float span
        int gcol = ((m >> 3) << 9) + u0 + (m & 7);
        const float4* wp = reinterpret_cast<const float4*>(Whh + (size_t)gcol * NH + kq);
        char* arow_hi = smem + OFF_AHI + m * SPITCH + kq * 2;
        char* arow_lo = smem + OFF_ALO + m * SPITCH + kq * 2;
#pragma unroll
        for (int i = 0; i < 16; i++) {
            float4 v = wp[i];
            __nv_bfloat16 hi[4], lo[4];
            split_bf16(v.x, hi[0], lo[0]); split_bf16(v.y, hi[1], lo[1]);
            split_bf16(v.z, hi[2], lo[2]); split_bf16(v.w, hi[3], lo[3]);
            *reinterpret_cast<uint2*>(arow_hi + i * 8) = *reinterpret_cast<uint2*>(hi);
            *reinterpret_cast<uint2*>(arow_lo + i * 8) = *reinterpret_cast<uint2*>(lo);
        }
    }
    __syncthreads();

    // ldmatrix base addresses (R5/R6 hardware-proven mappings; pitch = SPITCH)
    const uint32_t a_base_hi = sb + OFF_AHI + (mtw * 16 + (lane & 15)) * SPITCH + ((lane >> 4) << 4);
    const uint32_t a_base_lo = a_base_hi + (OFF_ALO - OFF_AHI);
    const uint32_t b_base_hi = sb + OFF_BHI
        + (ntw * 16 + (lane & 7) + ((lane >> 4) << 3)) * SPITCH + (((lane >> 3) & 1) << 4);
    const uint32_t b_base_lo = b_base_hi + (OFF_BLO - OFF_BHI);
    const int kh_off = kh * 512;           // byte offset of this warp's K half

    // activation binding: thread <-> (batch, unit), loop-invariant
    const int ab = tid >> 3;          // batch 0..31
    const int auu = tid & 7;          // unit 0..7
    float c_reg = 0.f;

    // prefetch xw for t = 0
    float xwp0, xwp1, xwp2, xwp3;
    {
        const int tt0 = grp ? (NT - 1) : 0;
        const size_t xrow = ((size_t)ab * NT + tt0) * NG + u0 + auu;
        xwp0 = __ldcg(xw + xrow);
        xwp1 = __ldcg(xw + xrow + 512);
        xwp2 = __ldcg(xw + xrow + 1024);
        xwp3 = __ldcg(xw + xrow + 1536);
    }

    unsigned target = 64u;
    for (int t = 0; t < NT; t++) {
        const int tt = grp ? (NT - 1 - t) : t;

        if (t > 0) {
            const __nv_bfloat16* hb_hi = ((t - 1) & 1) ? hb_hi1 : hb_hi0;
            const __nv_bfloat16* hb_lo = ((t - 1) & 1) ? hb_lo1 : hb_lo0;
            // ---- stage h (32 x 512 bf16 hi/lo) global -> smem (R9-proven __ldcg path) ----
#pragma unroll
            for (int i = 0; i < 8; i++) {
                int idx = i * 256 + tid;          // 0..2047
                int b = idx >> 6, c = idx & 63;
                uint4 vhi = __ldcg(reinterpret_cast<const uint4*>(hb_hi + b * NH + c * 8));
                uint4 vlo = __ldcg(reinterpret_cast<const uint4*>(hb_lo + b * NH + c * 8));
                *reinterpret_cast<uint4*>(smem + OFF_BHI + b * SPITCH + c * 16) = vhi;
                *reinterpret_cast<uint4*>(smem + OFF_BLO + b * SPITCH + c * 16) = vlo;
            }
            __syncthreads();

            // ---- HMMA: partial D(32x32) over this warp's K half ----
            float df[2][4];
#pragma unroll
            for (int nt = 0; nt < 2; nt++)
#pragma unroll
                for (int q = 0; q < 4; q++) df[nt][q] = 0.f;

#pragma unroll 4
            for (int ks = 0; ks < 16; ks++) {
                const int kb = kh_off + ks * 32;
                uint32_t ah[4], al[4];
                ldsm4(ah[0], ah[1], ah[2], ah[3], a_base_hi + kb);
                ldsm4(al[0], al[1], al[2], al[3], a_base_lo + kb);
                uint32_t r0, r1, r2, r3;
                uint32_t bh[2][2], bl[2][2];
                ldsm4(r0, r1, r2, r3, b_base_hi + kb);
                bh[0][0] = r0; bh[0][1] = r1; bh[1][0] = r2; bh[1][1] = r3;
                ldsm4(r0, r1, r2, r3, b_base_lo + kb);
                bl[0][0] = r0; bl[0][1] = r1; bl[1][0] = r2; bl[1][1] = r3;
#pragma unroll
                for (int nt = 0; nt < 2; nt++) {
                    mma16816(df[nt], ah, bh[nt]);
                    mma16816(df[nt], ah, bl[nt]);
                    mma16816(df[nt], al, bh[nt]);
                }
            }

            // ---- write partial D frags (pitch 36) ----
            {
                float* Dp = kh ? D1 : D0;
                int drow = mtw * 16 + (lane >> 2);
                int dcol = ntw * 16 + (lane & 3) * 2;
#pragma unroll
                for (int nt = 0; nt < 2; nt++) {
                    *reinterpret_cast<float2*>(&Dp[drow * 36 + dcol + nt * 8]) =
                        make_float2(df[nt][0], df[nt][1]);
                    *reinterpret_cast<float2*>(&Dp[(drow + 8) * 36 + dcol + nt * 8]) =
                        make_float2(df[nt][2], df[nt][3]);
                }
            }
        }
        __syncthreads();

        // ---- activation + c/h update (one (b,uu) pair per thread) ----
        {
            float gi = xwp0, gf = xwp1, gg = xwp2, go = xwp3;
            if (t > 0) {
                gi += D0[(0  + auu) * 36 + ab] + D1[(0  + auu) * 36 + ab];
                gf += D0[(8  + auu) * 36 + ab] + D1[(8  + auu) * 36 + ab];
                gg += D0[(16 + auu) * 36 + ab] + D1[(16 + auu) * 36 + ab];
                go += D0[(24 + auu) * 36 + ab] + D1[(24 + auu) * 36 + ab];
            }
            float cn = sigf(gf) * c_reg + sigf(gi) * tanhf(gg);
            float h  = sigf(go) * tanhf(cn);
            c_reg = cn;
            out[((size_t)ab * NT + tt) * (2 * NH) + grp * NH + u0 + auu] = h;
            __nv_bfloat16 hi, lo;
            split_bf16(h, hi, lo);
            if (t & 1) {
                hb_hi1[ab * NH + u0 + auu] = hi;
                hb_lo1[ab * NH + u0 + auu] = lo;
            } else {
                hb_hi0[ab * NH + u0 + auu] = hi;
                hb_lo0[ab * NH + u0 + auu] = lo;
            }
            if (layer == 0) {
                // fused convA: layer-1 GEMM A operand, row = b*NT+tt, col = grp*512+u
                size_t aidx = ((size_t)ab * NT + tt) * 1024 + grp * NH + u0 + auu;
                g_Ahi[aidx] = hi;
                g_Alo[aidx] = lo;
            }
        }

        // ---- group barrier; next xw prefetch hides behind the spin ----
        __threadfence();
        __syncthreads();
        if (tid == 0) atomicAdd(&g_cnt[grp], 1u);
        if (t + 1 < NT) {
            const int tt2 = grp ? (NT - 2 - t) : (t + 1);
            const size_t xrow = ((size_t)ab * NT + tt2) * NG + u0 + auu;
            xwp0 = __ldcg(xw + xrow);
            xwp1 = __ldcg(xw + xrow + 512);
            xwp2 = __ldcg(xw + xrow + 1024);
            xwp3 = __ldcg(xw + xrow + 1536);
        }
        if (tid == 0) {
            while (ld_acq(&g_cnt[grp]) < target) { __nanosleep(64); }
        }
        __syncthreads();
        target += 64u;
    }
}

// ---------------- classifier weight transpose ----------------
__global__ void k_wct(const float* __restrict__ Wc) {
    int i = blockIdx.x * 256 + threadIdx.x;
    if (i < NF * NC) {
        int f = i >> 5, c = i & 31;
        g_WcT[f * NC + c] = Wc[(size_t)c * NF + f];
    }
}

// ---------------- classifier + log-softmax, output (B, C, T) ----------------
__global__ __launch_bounds__(256) void k_cls(const float* __restrict__ truth,
                                             const int* __restrict__ tf,
                                             const float* __restrict__ bc,
                                             float* __restrict__ outp) {
    int warp = threadIdx.x >> 5;
    int lane = threadIdx.x & 31;
    int pos = blockIdx.x * 8 + warp;
    int b = pos >> 9, t = pos & 511;

    float acc = bc[lane];
    float past = 0.f;
    if (tf[0] != 0 && t > 0) past = truth[b * NT + t - 1];
    acc += past * g_WcT[lane];

    const float4* h4 = reinterpret_cast<const float4*>(g_h2 + ((size_t)b * NT + t) * (2 * NH));
    const float* wt = g_WcT + NC;
#pragma unroll 4
    for (int f4 = 0; f4 < 256; f4++) {
        float4 hv = h4[f4];
        int f = f4 * 4;
        acc += hv.x * wt[(f + 0) * NC + lane];
        acc += hv.y * wt[(f + 1) * NC + lane];
        acc += hv.z * wt[(f + 2) * NC + lane];
        acc += hv.w * wt[(f + 3) * NC + lane];
    }

    float m = acc;
#pragma unroll
    for (int o = 16; o > 0; o >>= 1) m = fmaxf(m, __shfl_xor_sync(0xffffffffu, m, o));
    float e = expf(acc - m);
    float s = e;
#pragma unroll
    for (int o = 16; o > 0; o >>= 1) s += __shfl_xor_sync(0xffffffffu, s, o);
    float y = acc - m - logf(s);

    outp[((size_t)b * NC + lane) * NT + t] = y;
}

// ---------------- launch ----------------
extern "C" void kernel_launch(void* const* d_in, const int* in_sizes, int n_in,
                              void* d_out, int out_size) {
    const int*   x     = (const int*)d_in[0];
    const float* truth = (const float*)d_in[1];
    const int*   tf    = (const int*)d_in[2];
    const float* emb   = (const float*)d_in[3];
    const float* Wih0f = (const float*)d_in[4];
    const float* Whh0f = (const float*)d_in[5];
    const float* bih0f = (const float*)d_in[6];
    const float* bhh0f = (const float*)d_in[7];
    const float* Wih0b = (const float*)d_in[8];
    const float* Whh0b = (const float*)d_in[9];
    const float* bih0b = (const float*)d_in[10];
    const float* bhh0b = (const float*)d_in[11];
    const float* Wih1f = (const float*)d_in[12];
    const float* Whh1f = (const float*)d_in[13];
    const float* bih1f = (const float*)d_in[14];
    const float* bhh1f = (const float*)d_in[15];
    const float* Wih1b = (const float*)d_in[16];
    const float* Whh1b = (const float*)d_in[17];
    const float* bih1b = (const float*)d_in[18];
    const float* bhh1b = (const float*)d_in[19];
    const float* Wc    = (const float*)d_in[20];
    const float* bc    = (const float*)d_in[21];

    cudaFuncSetAttribute(k_scan_tc, cudaFuncAttributeMaxDynamicSharedMemorySize, SCAN_SMEM);
    cudaFuncSetAttribute(k_gemm_bf16, cudaFuncAttributeMaxDynamicSharedMemorySize, GSMEM);

    dim3 ggrid(16, 128);
    const int w0_n4 = NG * 512 / 4;
    const int w1_n4 = NG * 1024 / 4;

    // ---- layer 0 (K = 512) ----
    k_embed<<<NM, 128>>>(x, emb);                                   // -> g_Ahi/g_Alo
    k_init<<<1, 32>>>();
    k_convW<<<(w0_n4 + 255) / 256, 256>>>(Wih0f, w0_n4);
    k_gemm_bf16<<<ggrid, 256, GSMEM>>>(0, bih0f, bhh0f, 512);
    k_convW<<<(w0_n4 + 255) / 256, 256>>>(Wih0b, w0_n4);
    k_gemm_bf16<<<ggrid, 256, GSMEM>>>(1, bih0b, bhh0b, 512);
    k_scan_tc<<<128, 256, SCAN_SMEM>>>(Whh0f, Whh0b, 0);            // also fills g_Ahi/g_Alo

    // ---- layer 1 (K = 1024) ----
    k_init<<<1, 32>>>();
    k_convW<<<(w1_n4 + 255) / 256, 256>>>(Wih1f, w1_n4);
    k_gemm_bf16<<<ggrid, 256, GSMEM>>>(0, bih1f, bhh1f, 1024);
    k_convW<<<(w1_n4 + 255) / 256, 256>>>(Wih1b, w1_n4);
    k_gemm_bf16<<<ggrid, 256, GSMEM>>>(1, bih1b, bhh1b, 1024);
    k_scan_tc<<<128, 256, SCAN_SMEM>>>(Whh1f, Whh1b, 1);

    // ---- classifier ----
    k_wct<<<(NF * NC + 255) / 256, 256>>>(Wc);
    k_cls<<<NM / 8, 256>>>(truth, tf, bc, (float*)d_out);

    (void)in_sizes; (void)n_in; (void)out_size;
}